// round 1
// baseline (speedup 1.0000x reference)
#include <cuda_runtime.h>
#include <cuda_bf16.h>
#include <math.h>

#define BQn   4096
#define Sn    8
#define Dn    512
#define MDn   128
#define Ln    6
#define FFNn  2048
#define TDn   32
#define ROWSn (BQn * Sn)          /* 32768 */
#define SCALE 0.17677669529663687f /* 32^-0.5 */

// ---------------- scratch (device globals; no allocation allowed) -----------
__device__ float g_X   [ROWSn * Dn];
__device__ float g_Qb  [ROWSn * Dn];
__device__ float g_Kb  [ROWSn * Dn];
__device__ float g_Vb  [ROWSn * Dn];
__device__ float g_Ctx [ROWSn * Dn];
__device__ float g_Out1[ROWSn * Dn];
__device__ float g_Ffn [ROWSn * FFNn];
__device__ float g_Bias[Ln * BQn * 64];
__device__ float g_Tseq[BQn * Sn];
__device__ float g_Hc  [BQn * MDn];
__device__ float g_Stats[2];

// ---------------- prep kernels ----------------------------------------------
__global__ void prep_x_kernel(const float* __restrict__ sup,
                              const float* __restrict__ cls) {
    int row = blockIdx.x;              // bq*8 + s
    int s   = row & 7;
    int bq  = row >> 3;
    int b   = bq >> 5;                 // Q = 32
    int t   = threadIdx.x;             // 0..127
    float v = (s == 0) ? cls[t] : sup[(b * 7 + (s - 1)) * MDn + t];
#pragma unroll
    for (int h = 0; h < 4; h++)
        g_X[row * Dn + h * MDn + t] = v;
}

__global__ void prep_t_kernel(const float* __restrict__ query_t,
                              const float* __restrict__ support_t) {
    int bq = blockIdx.x * blockDim.x + threadIdx.x;
    if (bq >= BQn) return;
    int b = bq >> 5, q = bq & 31;
    g_Tseq[bq * 8] = query_t[b * 32 + q];
#pragma unroll
    for (int f = 0; f < 7; f++)
        g_Tseq[bq * 8 + 1 + f] = support_t[b * 7 + f];
}

__global__ void prep_bias_kernel(const float* __restrict__ t_freq,
                                 const float* __restrict__ t_phase,
                                 const float* __restrict__ time_w) {
    int bq  = blockIdx.x;
    int tid = threadIdx.x;             // 64
    __shared__ float tw[Ln][TDn];
    __shared__ float fr[TDn], ph[TDn], ts[Sn];
    if (tid < TDn) { fr[tid] = t_freq[tid]; ph[tid] = t_phase[tid]; }
    if (tid < Sn)  ts[tid] = g_Tseq[bq * 8 + tid];
    for (int i = tid; i < Ln * TDn; i += 64) tw[i / TDn][i % TDn] = time_w[i];
    __syncthreads();
    int s = tid >> 3, t = tid & 7;
    float dt = ts[s] - ts[t];
    float acc[Ln];
#pragma unroll
    for (int l = 0; l < Ln; l++) acc[l] = 0.f;
    for (int td = 0; td < TDn; td++) {
        float c = cosf(dt * fr[td] + ph[td]);
#pragma unroll
        for (int l = 0; l < Ln; l++) acc[l] += c * tw[l][td];
    }
#pragma unroll
    for (int l = 0; l < Ln; l++)
        g_Bias[(l * BQn + bq) * 64 + tid] = acc[l];
}

// ---------------- SGEMM: C[M,N] = A[M,K(lda)] @ W[K,N] + bias (opt gelu) ----
__global__ __launch_bounds__(256, 2)
void sgemm_kernel(const float* __restrict__ A, const float* __restrict__ W,
                  const float* __restrict__ bias, float* __restrict__ C,
                  int M, int N, int K, int lda, int act) {
    __shared__ float As[8][128];
    __shared__ float Bs[8][128];
    const int tid = threadIdx.x;
    const int rowBase = blockIdx.y * 128;
    const int colBase = blockIdx.x * 128;
    const int ty = tid >> 4, tx = tid & 15;

    const int aRow = tid >> 1;
    const int aK   = (tid & 1) * 4;
    const int bRow = tid >> 5;
    const int bC4  = (tid & 31) * 4;
    const float* Ap = A + (rowBase + aRow) * lda + aK;
    const float* Wp = W + bRow * N + colBase + bC4;

    float acc[8][8];
#pragma unroll
    for (int i = 0; i < 8; i++)
#pragma unroll
        for (int j = 0; j < 8; j++) acc[i][j] = 0.f;

    for (int k0 = 0; k0 < K; k0 += 8) {
        float4 a = *(const float4*)(Ap + k0);
        As[aK + 0][aRow] = a.x;
        As[aK + 1][aRow] = a.y;
        As[aK + 2][aRow] = a.z;
        As[aK + 3][aRow] = a.w;
        *(float4*)&Bs[bRow][bC4] = *(const float4*)(Wp + (size_t)k0 * N);
        __syncthreads();
#pragma unroll
        for (int kk = 0; kk < 8; kk++) {
            float ra[8], rb[8];
#pragma unroll
            for (int i = 0; i < 8; i++) ra[i] = As[kk][ty * 8 + i];
#pragma unroll
            for (int j = 0; j < 4; j++) {
                rb[j]     = Bs[kk][tx * 4 + j];
                rb[j + 4] = Bs[kk][64 + tx * 4 + j];
            }
#pragma unroll
            for (int i = 0; i < 8; i++)
#pragma unroll
                for (int j = 0; j < 8; j++) acc[i][j] = fmaf(ra[i], rb[j], acc[i][j]);
        }
        __syncthreads();
    }
#pragma unroll
    for (int i = 0; i < 8; i++) {
        int row = rowBase + ty * 8 + i;
#pragma unroll
        for (int j = 0; j < 8; j++) {
            int col = colBase + ((j < 4) ? (tx * 4 + j) : (64 + tx * 4 + j - 4));
            float v = acc[i][j] + bias[col];
            if (act) { // gelu tanh
                float x3 = v * v * v;
                v = 0.5f * v * (1.f + tanhf(0.7978845608028654f * (v + 0.044715f * x3)));
            }
            C[(size_t)row * N + col] = v;
        }
    }
}

// ---------------- attention (raw-reshape semantics; tiny S=8) ---------------
__global__ void attn_kernel(const float* __restrict__ bias) {
    int j   = blockIdx.x;              // 0..BQ*H-1
    int tid = threadIdx.x;             // 128
    __shared__ float qs[8][128], ks[8][128], vs[8][128];
    __shared__ float sc[8][9];
    const float* qp = g_Qb + (size_t)j * 1024;
    const float* kp = g_Kb + (size_t)j * 1024;
    const float* vp = g_Vb + (size_t)j * 1024;
#pragma unroll
    for (int s = 0; s < 8; s++) {
        qs[s][tid] = qp[s * 128 + tid];
        ks[s][tid] = kp[s * 128 + tid];
        vs[s][tid] = vp[s * 128 + tid];
    }
    __syncthreads();
    if (tid < 64) {
        int s = tid >> 3, t = tid & 7;
        float d = 0.f;
#pragma unroll
        for (int i = 0; i < 128; i++) d = fmaf(qs[s][i], ks[t][i], d);
        sc[s][t] = d * SCALE + bias[(j & (BQn - 1)) * 64 + tid];
    }
    __syncthreads();
    if (tid < 8) {
        int s = tid;
        float m = sc[s][0];
#pragma unroll
        for (int t = 1; t < 8; t++) m = fmaxf(m, sc[s][t]);
        float sum = 0.f;
#pragma unroll
        for (int t = 0; t < 8; t++) { float e = expf(sc[s][t] - m); sc[s][t] = e; sum += e; }
        float inv = 1.f / sum;
#pragma unroll
        for (int t = 0; t < 8; t++) sc[s][t] *= inv;
    }
    __syncthreads();
    float* cp = g_Ctx + (size_t)j * 1024;
#pragma unroll
    for (int s = 0; s < 8; s++) {
        float a = 0.f;
#pragma unroll
        for (int t = 0; t < 8; t++) a = fmaf(sc[s][t], vs[t][tid], a);
        cp[s * 128 + tid] = a;
    }
}

// ---------------- residual add + LayerNorm ----------------------------------
__global__ void add_ln_kernel(const float* __restrict__ res, const float* __restrict__ add,
                              const float* __restrict__ g, const float* __restrict__ b,
                              float* __restrict__ out) {
    int row = blockIdx.x;
    int tid = threadIdx.x;             // 256
    float v0 = res[(size_t)row * Dn + tid]       + add[(size_t)row * Dn + tid];
    float v1 = res[(size_t)row * Dn + tid + 256] + add[(size_t)row * Dn + tid + 256];
    float s  = v0 + v1;
    float sq = v0 * v0 + v1 * v1;
#pragma unroll
    for (int o = 16; o > 0; o >>= 1) {
        s  += __shfl_xor_sync(0xffffffffu, s,  o);
        sq += __shfl_xor_sync(0xffffffffu, sq, o);
    }
    __shared__ float rs[8], rq[8];
    __shared__ float s_mean, s_inv;
    int w = tid >> 5;
    if ((tid & 31) == 0) { rs[w] = s; rq[w] = sq; }
    __syncthreads();
    if (tid == 0) {
        float ts = 0.f, tq = 0.f;
#pragma unroll
        for (int i = 0; i < 8; i++) { ts += rs[i]; tq += rq[i]; }
        float mean = ts * (1.f / Dn);
        float var  = tq * (1.f / Dn) - mean * mean;
        s_mean = mean;
        s_inv  = rsqrtf(var + 1e-5f);
    }
    __syncthreads();
    float mean = s_mean, inv = s_inv;
    out[(size_t)row * Dn + tid]       = g[tid]       * (v0 - mean) * inv + b[tid];
    out[(size_t)row * Dn + tid + 256] = g[tid + 256] * (v1 - mean) * inv + b[tid + 256];
}

// ---------------- final BatchNorm (only s=0 channel needed) -----------------
__global__ void bn_zero_kernel() { g_Stats[0] = 0.f; g_Stats[1] = 0.f; }

__global__ void bn_reduce_kernel() {
    float s = 0.f, q = 0.f;
    for (int i = blockIdx.x * blockDim.x + threadIdx.x; i < BQn * MDn;
         i += gridDim.x * blockDim.x) {
        float v = g_Hc[i]; s += v; q += v * v;
    }
#pragma unroll
    for (int o = 16; o > 0; o >>= 1) {
        s += __shfl_xor_sync(0xffffffffu, s, o);
        q += __shfl_xor_sync(0xffffffffu, q, o);
    }
    __shared__ float rs[8], rq[8];
    int w = threadIdx.x >> 5;
    if ((threadIdx.x & 31) == 0) { rs[w] = s; rq[w] = q; }
    __syncthreads();
    if (threadIdx.x == 0) {
        float ts = 0.f, tq = 0.f;
#pragma unroll
        for (int i = 0; i < 8; i++) { ts += rs[i]; tq += rq[i]; }
        atomicAdd(&g_Stats[0], ts);
        atomicAdd(&g_Stats[1], tq);
    }
}

__global__ void bn_final_kernel(const float* __restrict__ bn_g,
                                const float* __restrict__ bn_b,
                                float* __restrict__ out) {
    const float invN = 1.f / (float)(BQn * MDn);
    float mu  = g_Stats[0] * invN;
    float var = g_Stats[1] * invN - mu * mu;
    float inv = rsqrtf(var + 1e-5f);
    float gg = bn_g[0], bb = bn_b[0];
    for (int i = blockIdx.x * blockDim.x + threadIdx.x; i < BQn * MDn;
         i += gridDim.x * blockDim.x) {
        float h = gg * (g_Hc[i] - mu) * inv + bb;
        out[i] = (h >= 0.f) ? h : 0.01f * h;
    }
}

// ---------------- host orchestration ----------------------------------------
static void launch_gemm(const float* A, const float* W, const float* bias, float* C,
                        int M, int N, int K, int lda, int act) {
    dim3 grid(N / 128, M / 128);
    sgemm_kernel<<<grid, 256>>>(A, W, bias, C, M, N, K, lda, act);
}

extern "C" void kernel_launch(void* const* d_in, const int* in_sizes, int n_in,
                              void* d_out, int out_size) {
    const float* sup    = (const float*)d_in[0];
    const float* qt     = (const float*)d_in[1];
    const float* st     = (const float*)d_in[2];
    const float* cls    = (const float*)d_in[3];
    const float* tfreq  = (const float*)d_in[4];
    const float* tphase = (const float*)d_in[5];
    const float* Wq = (const float*)d_in[6];
    const float* bq = (const float*)d_in[7];
    const float* Wk = (const float*)d_in[8];
    const float* bk = (const float*)d_in[9];
    const float* Wv = (const float*)d_in[10];
    const float* bv = (const float*)d_in[11];
    const float* Wo = (const float*)d_in[12];
    const float* bo = (const float*)d_in[13];
    const float* ln1g = (const float*)d_in[14];
    const float* ln1b = (const float*)d_in[15];
    const float* tw   = (const float*)d_in[16];
    const float* W1 = (const float*)d_in[17];
    const float* b1 = (const float*)d_in[18];
    const float* W2 = (const float*)d_in[19];
    const float* b2 = (const float*)d_in[20];
    const float* ln2g = (const float*)d_in[21];
    const float* ln2b = (const float*)d_in[22];
    const float* Wc = (const float*)d_in[23];
    const float* bc = (const float*)d_in[24];
    const float* bng = (const float*)d_in[25];
    const float* bnb = (const float*)d_in[26];
    float* out = (float*)d_out;

    float *X, *Qb, *Kb, *Vb, *Ctx, *Out1, *Ffn, *Hc, *Bias;
    cudaGetSymbolAddress((void**)&X,    g_X);
    cudaGetSymbolAddress((void**)&Qb,   g_Qb);
    cudaGetSymbolAddress((void**)&Kb,   g_Kb);
    cudaGetSymbolAddress((void**)&Vb,   g_Vb);
    cudaGetSymbolAddress((void**)&Ctx,  g_Ctx);
    cudaGetSymbolAddress((void**)&Out1, g_Out1);
    cudaGetSymbolAddress((void**)&Ffn,  g_Ffn);
    cudaGetSymbolAddress((void**)&Hc,   g_Hc);
    cudaGetSymbolAddress((void**)&Bias, g_Bias);

    prep_x_kernel<<<ROWSn, 128>>>(sup, cls);
    prep_t_kernel<<<16, 256>>>(qt, st);
    prep_bias_kernel<<<BQn, 64>>>(tfreq, tphase, tw);

    for (int l = 0; l < Ln; l++) {
        const float* Wq_ = Wq + (size_t)l * Dn * Dn;
        const float* Wk_ = Wk + (size_t)l * Dn * Dn;
        const float* Wv_ = Wv + (size_t)l * Dn * Dn;
        const float* Wo_ = Wo + (size_t)l * Dn * Dn;
        const float* W1_ = W1 + (size_t)l * Dn * FFNn;
        const float* W2_ = W2 + (size_t)l * FFNn * Dn;

        launch_gemm(X, Wq_, bq + l * Dn, Qb, ROWSn, Dn, Dn, Dn, 0);
        launch_gemm(X, Wk_, bk + l * Dn, Kb, ROWSn, Dn, Dn, Dn, 0);
        launch_gemm(X, Wv_, bv + l * Dn, Vb, ROWSn, Dn, Dn, Dn, 0);

        attn_kernel<<<BQn * 4, 128>>>(Bias + (size_t)l * BQn * 64);

        launch_gemm(Ctx, Wo_, bo + l * Dn, Qb, ROWSn, Dn, Dn, Dn, 0);     // reuse Qb
        add_ln_kernel<<<ROWSn, 256>>>(X, Qb, ln1g + l * Dn, ln1b + l * Dn, Out1);

        launch_gemm(Out1, W1_, b1 + l * FFNn, Ffn, ROWSn, FFNn, Dn, Dn, 1); // gelu
        launch_gemm(Ffn, W2_, b2 + l * Dn, Qb, ROWSn, Dn, FFNn, FFNn, 0);
        add_ln_kernel<<<ROWSn, 256>>>(Out1, Qb, ln2g + l * Dn, ln2b + l * Dn, X);
    }

    // compress: only s=0 rows feed the output (BN stats per s-channel, out uses s=0)
    launch_gemm(X, Wc, bc, Hc, BQn, MDn, Dn, Sn * Dn, 0);
    bn_zero_kernel<<<1, 1>>>();
    bn_reduce_kernel<<<256, 256>>>();
    bn_final_kernel<<<2048, 256>>>(bng, bnb, out);

    (void)in_sizes; (void)n_in; (void)out_size;
}

// round 3
// speedup vs baseline: 2.8328x; 2.8328x over previous
#include <cuda_runtime.h>
#include <cuda_bf16.h>
#include <math.h>
#include <stdint.h>

#define BQn   4096
#define Sn    8
#define Dn    512
#define MDn   128
#define Ln    6
#define FFNn  2048
#define TDn   32
#define ROWSn (BQn * Sn)          /* 32768 */
#define SCALE 0.17677669529663687f /* 32^-0.5 */

// ---------------- scratch (device globals; no allocation allowed) -----------
__device__ float g_X   [ROWSn * Dn];
__device__ float g_Qb  [ROWSn * Dn];
__device__ float g_Kb  [ROWSn * Dn];
__device__ float g_Vb  [ROWSn * Dn];
__device__ float g_Ctx [ROWSn * Dn];
__device__ float g_Out1[ROWSn * Dn];
__device__ float g_Ffn [ROWSn * FFNn];
__device__ float g_Bias[Ln * BQn * 64];
__device__ float g_Tseq[BQn * Sn];
__device__ float g_Hc  [BQn * MDn];
__device__ float g_Stats[2];
#define WT_TOTAL (Ln * (4 * Dn * Dn + 2 * Dn * FFNn))
__device__ float g_WT  [WT_TOTAL];

// ---------------- tf32 round helper -----------------------------------------
__device__ __forceinline__ float rna_tf32(float x) {
    float r;
    asm("cvt.rna.tf32.f32 %0, %1;" : "=f"(r) : "f"(x));
    return r;
}

__device__ __forceinline__ float gelu_tanh(float v) {
    return 0.5f * v * (1.f + tanhf(0.7978845608028654f * (v + 0.044715f * v * v * v)));
}

__device__ __forceinline__ uint32_t smem_u32(const void* p) {
    uint32_t a;
    asm("{ .reg .u64 t; cvta.to.shared.u64 t, %1; cvt.u32.u64 %0, t; }" : "=r"(a) : "l"(p));
    return a;
}

__device__ __forceinline__ void cp_async16(uint32_t saddr, const void* gaddr) {
    asm volatile("cp.async.ca.shared.global [%0], [%1], 16;" :: "r"(saddr), "l"(gaddr));
}
#define CP_COMMIT() asm volatile("cp.async.commit_group;" ::: "memory")
#define CP_WAIT1()  asm volatile("cp.async.wait_group 1;" ::: "memory")

__device__ __forceinline__ void mma_tf32(float* c, const uint32_t* a, const uint32_t* b) {
    asm volatile(
        "mma.sync.aligned.m16n8k8.row.col.f32.tf32.tf32.f32 "
        "{%0,%1,%2,%3}, {%4,%5,%6,%7}, {%8,%9}, {%0,%1,%2,%3};"
        : "+f"(c[0]), "+f"(c[1]), "+f"(c[2]), "+f"(c[3])
        : "r"(a[0]), "r"(a[1]), "r"(a[2]), "r"(a[3]), "r"(b[0]), "r"(b[1]));
}

// ---------------- tf32 mma.sync GEMM: C[M,N] = A[M,K(lda)] @ B[K,N] + bias --
// CTA tile 128x128, 8 warps (2x4), warp tile 64x32, K chunks of 32, 2-stage
// cp.async pipeline.  A pad 36 floats/row, B pad 132 floats/row.
#define AP 36
#define BP 132
#define A_STG (128 * AP)           /* floats per A stage */
#define B_STG (32 * BP)            /* floats per B stage */
#define TFG_SMEM ((2 * A_STG + 2 * B_STG) * 4)

__global__ __launch_bounds__(256, 2)
void tf32_gemm_kernel(const float* __restrict__ A, const float* __restrict__ B,
                      const float* __restrict__ bias, float* __restrict__ C,
                      int N, int K, int lda, int act, int rnd) {
    extern __shared__ float sm[];
    float* AsB = sm;                      // [2][128][AP]
    float* BsB = sm + 2 * A_STG;          // [2][32][BP]

    const int tid  = threadIdx.x;
    const int lane = tid & 31, warp = tid >> 5;
    const int wm = warp & 1, wn = warp >> 1;
    const int qr = lane >> 2, qc = lane & 3;
    const int rowBase = blockIdx.y * 128;
    const int colBase = blockIdx.x * 128;

    // cp.async thread mapping (4 x 16B chunks each for A and B)
    const int aRow = tid >> 1;                 // c = tid + i*256 -> row = c>>3 ... precompute per i below
    (void)aRow;

    float acc[4][4][4];
#pragma unroll
    for (int i = 0; i < 4; i++)
#pragma unroll
        for (int j = 0; j < 4; j++)
#pragma unroll
            for (int k = 0; k < 4; k++) acc[i][j][k] = 0.f;

    const int nKt = K >> 5;

    // ---- load helpers (inline) ----
    // A chunk: c = tid + i*256; row = c>>3, k4 = (c&7)*4
    // B chunk: c = tid + i*256; row = c>>5, n4 = (c&31)*4
    uint32_t asmem = smem_u32(AsB);
    uint32_t bsmem = smem_u32(BsB);

#define LOAD_TILE(kt, buf) do {                                                   \
    int _k0 = (kt) << 5;                                                          \
    _Pragma("unroll")                                                             \
    for (int _i = 0; _i < 4; _i++) {                                              \
        int _c = tid + _i * 256;                                                  \
        int _r = _c >> 3, _k4 = (_c & 7) << 2;                                    \
        cp_async16(asmem + (((buf) * A_STG + _r * AP + _k4) << 2),                \
                   A + (size_t)(rowBase + _r) * lda + _k0 + _k4);                 \
        int _rb = _c >> 5, _n4 = (_c & 31) << 2;                                  \
        cp_async16(bsmem + (((buf) * B_STG + _rb * BP + _n4) << 2),               \
                   B + (size_t)(_k0 + _rb) * N + colBase + _n4);                  \
    }                                                                             \
} while (0)

    LOAD_TILE(0, 0);
    CP_COMMIT();

    for (int kt = 0; kt < nKt; kt++) {
        int buf = kt & 1;
        if (kt + 1 < nKt) LOAD_TILE(kt + 1, buf ^ 1);
        CP_COMMIT();
        CP_WAIT1();
        __syncthreads();

        const uint32_t* a = (const uint32_t*)(AsB + buf * A_STG);
        const uint32_t* b = (const uint32_t*)(BsB + buf * B_STG);
#pragma unroll
        for (int ks = 0; ks < 4; ks++) {
            int kk = ks * 8;
            uint32_t af[4][4];
#pragma unroll
            for (int mt = 0; mt < 4; mt++) {
                int rb = wm * 64 + mt * 16;
                af[mt][0] = a[(rb + qr)     * AP + kk + qc];
                af[mt][1] = a[(rb + qr + 8) * AP + kk + qc];
                af[mt][2] = a[(rb + qr)     * AP + kk + qc + 4];
                af[mt][3] = a[(rb + qr + 8) * AP + kk + qc + 4];
            }
            uint32_t bf[4][2];
#pragma unroll
            for (int nt = 0; nt < 4; nt++) {
                int nb = wn * 32 + nt * 8;
                bf[nt][0] = b[(kk + qc)     * BP + nb + qr];
                bf[nt][1] = b[(kk + qc + 4) * BP + nb + qr];
            }
#pragma unroll
            for (int mt = 0; mt < 4; mt++)
#pragma unroll
                for (int nt = 0; nt < 4; nt++)
                    mma_tf32(acc[mt][nt], af[mt], bf[nt]);
        }
        __syncthreads();
    }

    // ---- epilogue ----
#pragma unroll
    for (int mt = 0; mt < 4; mt++) {
        int row0 = rowBase + wm * 64 + mt * 16 + qr;
#pragma unroll
        for (int nt = 0; nt < 4; nt++) {
            int col = colBase + wn * 32 + nt * 8 + qc * 2;
            float b0 = bias[col], b1 = bias[col + 1];
            float v0 = acc[mt][nt][0] + b0;
            float v1 = acc[mt][nt][1] + b1;
            float v2 = acc[mt][nt][2] + b0;
            float v3 = acc[mt][nt][3] + b1;
            if (act) { v0 = gelu_tanh(v0); v1 = gelu_tanh(v1); v2 = gelu_tanh(v2); v3 = gelu_tanh(v3); }
            if (rnd) { v0 = rna_tf32(v0); v1 = rna_tf32(v1); v2 = rna_tf32(v2); v3 = rna_tf32(v3); }
            float2 p0 = make_float2(v0, v1);
            float2 p1 = make_float2(v2, v3);
            *(float2*)(C + (size_t)row0 * N + col)       = p0;
            *(float2*)(C + (size_t)(row0 + 8) * N + col) = p1;
        }
    }
#undef LOAD_TILE
}

// ---------------- weight rounding (copy with rna to tf32) -------------------
__global__ void rna_copy_kernel(const float* __restrict__ src, float* __restrict__ dst, int n) {
    for (int i = blockIdx.x * blockDim.x + threadIdx.x; i < n; i += gridDim.x * blockDim.x)
        dst[i] = rna_tf32(src[i]);
}

// ---------------- prep kernels ----------------------------------------------
__global__ void prep_x_kernel(const float* __restrict__ sup,
                              const float* __restrict__ cls) {
    int row = blockIdx.x;
    int s   = row & 7;
    int bq  = row >> 3;
    int b   = bq >> 5;
    int t   = threadIdx.x;
    float v = (s == 0) ? cls[t] : sup[(b * 7 + (s - 1)) * MDn + t];
    v = rna_tf32(v);
#pragma unroll
    for (int h = 0; h < 4; h++)
        g_X[row * Dn + h * MDn + t] = v;
}

__global__ void prep_t_kernel(const float* __restrict__ query_t,
                              const float* __restrict__ support_t) {
    int bq = blockIdx.x * blockDim.x + threadIdx.x;
    if (bq >= BQn) return;
    int b = bq >> 5, q = bq & 31;
    g_Tseq[bq * 8] = query_t[b * 32 + q];
#pragma unroll
    for (int f = 0; f < 7; f++)
        g_Tseq[bq * 8 + 1 + f] = support_t[b * 7 + f];
}

__global__ void prep_bias_kernel(const float* __restrict__ t_freq,
                                 const float* __restrict__ t_phase,
                                 const float* __restrict__ time_w) {
    int bq  = blockIdx.x;
    int tid = threadIdx.x;             // 64
    __shared__ float tw[Ln][TDn];
    __shared__ float fr[TDn], ph[TDn], ts[Sn];
    if (tid < TDn) { fr[tid] = t_freq[tid]; ph[tid] = t_phase[tid]; }
    if (tid < Sn)  ts[tid] = g_Tseq[bq * 8 + tid];
    for (int i = tid; i < Ln * TDn; i += 64) tw[i / TDn][i % TDn] = time_w[i];
    __syncthreads();
    int s = tid >> 3, t = tid & 7;
    float dt = ts[s] - ts[t];
    float acc[Ln];
#pragma unroll
    for (int l = 0; l < Ln; l++) acc[l] = 0.f;
    for (int td = 0; td < TDn; td++) {
        float c = cosf(dt * fr[td] + ph[td]);
#pragma unroll
        for (int l = 0; l < Ln; l++) acc[l] += c * tw[l][td];
    }
#pragma unroll
    for (int l = 0; l < Ln; l++)
        g_Bias[(l * BQn + bq) * 64 + tid] = acc[l];
}

// ---------------- fp32 SGEMM (used only for the small Wc projection) --------
__global__ __launch_bounds__(256, 2)
void sgemm_kernel(const float* __restrict__ A, const float* __restrict__ W,
                  const float* __restrict__ bias, float* __restrict__ C,
                  int M, int N, int K, int lda, int act) {
    __shared__ float As[8][128];
    __shared__ float Bs[8][128];
    const int tid = threadIdx.x;
    const int rowBase = blockIdx.y * 128;
    const int colBase = blockIdx.x * 128;
    const int ty = tid >> 4, tx = tid & 15;

    const int aRow = tid >> 1;
    const int aK   = (tid & 1) * 4;
    const int bRow = tid >> 5;
    const int bC4  = (tid & 31) * 4;
    const float* Ap = A + (rowBase + aRow) * lda + aK;
    const float* Wp = W + bRow * N + colBase + bC4;

    float acc[8][8];
#pragma unroll
    for (int i = 0; i < 8; i++)
#pragma unroll
        for (int j = 0; j < 8; j++) acc[i][j] = 0.f;

    for (int k0 = 0; k0 < K; k0 += 8) {
        float4 a = *(const float4*)(Ap + k0);
        As[aK + 0][aRow] = a.x;
        As[aK + 1][aRow] = a.y;
        As[aK + 2][aRow] = a.z;
        As[aK + 3][aRow] = a.w;
        *(float4*)&Bs[bRow][bC4] = *(const float4*)(Wp + (size_t)k0 * N);
        __syncthreads();
#pragma unroll
        for (int kk = 0; kk < 8; kk++) {
            float ra[8], rb[8];
#pragma unroll
            for (int i = 0; i < 8; i++) ra[i] = As[kk][ty * 8 + i];
#pragma unroll
            for (int j = 0; j < 4; j++) {
                rb[j]     = Bs[kk][tx * 4 + j];
                rb[j + 4] = Bs[kk][64 + tx * 4 + j];
            }
#pragma unroll
            for (int i = 0; i < 8; i++)
#pragma unroll
                for (int j = 0; j < 8; j++) acc[i][j] = fmaf(ra[i], rb[j], acc[i][j]);
        }
        __syncthreads();
    }
#pragma unroll
    for (int i = 0; i < 8; i++) {
        int row = rowBase + ty * 8 + i;
#pragma unroll
        for (int j = 0; j < 8; j++) {
            int col = colBase + ((j < 4) ? (tx * 4 + j) : (64 + tx * 4 + j - 4));
            float v = acc[i][j] + bias[col];
            if (act) {
                float x3 = v * v * v;
                v = 0.5f * v * (1.f + tanhf(0.7978845608028654f * (v + 0.044715f * x3)));
            }
            C[(size_t)row * N + col] = v;
        }
    }
}

// ---------------- attention (raw-reshape semantics; tiny S=8) ---------------
__global__ void attn_kernel(const float* __restrict__ bias) {
    int j   = blockIdx.x;
    int tid = threadIdx.x;             // 128
    __shared__ float qs[8][128], ks[8][128], vs[8][128];
    __shared__ float sc[8][9];
    const float* qp = g_Qb + (size_t)j * 1024;
    const float* kp = g_Kb + (size_t)j * 1024;
    const float* vp = g_Vb + (size_t)j * 1024;
#pragma unroll
    for (int s = 0; s < 8; s++) {
        qs[s][tid] = qp[s * 128 + tid];
        ks[s][tid] = kp[s * 128 + tid];
        vs[s][tid] = vp[s * 128 + tid];
    }
    __syncthreads();
    if (tid < 64) {
        int s = tid >> 3, t = tid & 7;
        float d = 0.f;
#pragma unroll
        for (int i = 0; i < 128; i++) d = fmaf(qs[s][i], ks[t][i], d);
        sc[s][t] = d * SCALE + bias[(j & (BQn - 1)) * 64 + tid];
    }
    __syncthreads();
    if (tid < 8) {
        int s = tid;
        float m = sc[s][0];
#pragma unroll
        for (int t = 1; t < 8; t++) m = fmaxf(m, sc[s][t]);
        float sum = 0.f;
#pragma unroll
        for (int t = 0; t < 8; t++) { float e = expf(sc[s][t] - m); sc[s][t] = e; sum += e; }
        float inv = 1.f / sum;
#pragma unroll
        for (int t = 0; t < 8; t++) sc[s][t] *= inv;
    }
    __syncthreads();
    float* cp = g_Ctx + (size_t)j * 1024;
#pragma unroll
    for (int s = 0; s < 8; s++) {
        float a = 0.f;
#pragma unroll
        for (int t = 0; t < 8; t++) a = fmaf(sc[s][t], vs[t][tid], a);
        cp[s * 128 + tid] = rna_tf32(a);
    }
}

// ---------------- residual add + LayerNorm (tf32-rounded output) ------------
__global__ void add_ln_kernel(const float* __restrict__ res, const float* __restrict__ add,
                              const float* __restrict__ g, const float* __restrict__ b,
                              float* __restrict__ out) {
    int row = blockIdx.x;
    int tid = threadIdx.x;             // 256
    float v0 = res[(size_t)row * Dn + tid]       + add[(size_t)row * Dn + tid];
    float v1 = res[(size_t)row * Dn + tid + 256] + add[(size_t)row * Dn + tid + 256];
    float s  = v0 + v1;
    float sq = v0 * v0 + v1 * v1;
#pragma unroll
    for (int o = 16; o > 0; o >>= 1) {
        s  += __shfl_xor_sync(0xffffffffu, s,  o);
        sq += __shfl_xor_sync(0xffffffffu, sq, o);
    }
    __shared__ float rs[8], rq[8];
    __shared__ float s_mean, s_inv;
    int w = tid >> 5;
    if ((tid & 31) == 0) { rs[w] = s; rq[w] = sq; }
    __syncthreads();
    if (tid == 0) {
        float ts = 0.f, tq = 0.f;
#pragma unroll
        for (int i = 0; i < 8; i++) { ts += rs[i]; tq += rq[i]; }
        float mean = ts * (1.f / Dn);
        float var  = tq * (1.f / Dn) - mean * mean;
        s_mean = mean;
        s_inv  = rsqrtf(var + 1e-5f);
    }
    __syncthreads();
    float mean = s_mean, inv = s_inv;
    out[(size_t)row * Dn + tid]       = rna_tf32(g[tid]       * (v0 - mean) * inv + b[tid]);
    out[(size_t)row * Dn + tid + 256] = rna_tf32(g[tid + 256] * (v1 - mean) * inv + b[tid + 256]);
}

// ---------------- final BatchNorm (only s=0 channel needed) -----------------
__global__ void bn_zero_kernel() { g_Stats[0] = 0.f; g_Stats[1] = 0.f; }

__global__ void bn_reduce_kernel() {
    float s = 0.f, q = 0.f;
    for (int i = blockIdx.x * blockDim.x + threadIdx.x; i < BQn * MDn;
         i += gridDim.x * blockDim.x) {
        float v = g_Hc[i]; s += v; q += v * v;
    }
#pragma unroll
    for (int o = 16; o > 0; o >>= 1) {
        s += __shfl_xor_sync(0xffffffffu, s, o);
        q += __shfl_xor_sync(0xffffffffu, q, o);
    }
    __shared__ float rs[8], rq[8];
    int w = threadIdx.x >> 5;
    if ((threadIdx.x & 31) == 0) { rs[w] = s; rq[w] = q; }
    __syncthreads();
    if (threadIdx.x == 0) {
        float ts = 0.f, tq = 0.f;
#pragma unroll
        for (int i = 0; i < 8; i++) { ts += rs[i]; tq += rq[i]; }
        atomicAdd(&g_Stats[0], ts);
        atomicAdd(&g_Stats[1], tq);
    }
}

__global__ void bn_final_kernel(const float* __restrict__ bn_g,
                                const float* __restrict__ bn_b,
                                float* __restrict__ out) {
    const float invN = 1.f / (float)(BQn * MDn);
    float mu  = g_Stats[0] * invN;
    float var = g_Stats[1] * invN - mu * mu;
    float inv = rsqrtf(var + 1e-5f);
    float gg = bn_g[0], bb = bn_b[0];
    for (int i = blockIdx.x * blockDim.x + threadIdx.x; i < BQn * MDn;
         i += gridDim.x * blockDim.x) {
        float h = gg * (g_Hc[i] - mu) * inv + bb;
        out[i] = (h >= 0.f) ? h : 0.01f * h;
    }
}

// ---------------- host orchestration ----------------------------------------
extern "C" void kernel_launch(void* const* d_in, const int* in_sizes, int n_in,
                              void* d_out, int out_size) {
    const float* sup    = (const float*)d_in[0];
    const float* qt     = (const float*)d_in[1];
    const float* st     = (const float*)d_in[2];
    const float* cls    = (const float*)d_in[3];
    const float* tfreq  = (const float*)d_in[4];
    const float* tphase = (const float*)d_in[5];
    const float* Wq = (const float*)d_in[6];
    const float* bq = (const float*)d_in[7];
    const float* Wk = (const float*)d_in[8];
    const float* bk = (const float*)d_in[9];
    const float* Wv = (const float*)d_in[10];
    const float* bv = (const float*)d_in[11];
    const float* Wo = (const float*)d_in[12];
    const float* bo = (const float*)d_in[13];
    const float* ln1g = (const float*)d_in[14];
    const float* ln1b = (const float*)d_in[15];
    const float* tw   = (const float*)d_in[16];
    const float* W1 = (const float*)d_in[17];
    const float* b1 = (const float*)d_in[18];
    const float* W2 = (const float*)d_in[19];
    const float* b2 = (const float*)d_in[20];
    const float* ln2g = (const float*)d_in[21];
    const float* ln2b = (const float*)d_in[22];
    const float* Wc = (const float*)d_in[23];
    const float* bc = (const float*)d_in[24];
    const float* bng = (const float*)d_in[25];
    const float* bnb = (const float*)d_in[26];
    float* out = (float*)d_out;

    float *X, *Qb, *Kb, *Vb, *Ctx, *Out1, *Ffn, *Hc, *Bias, *WT;
    cudaGetSymbolAddress((void**)&X,    g_X);
    cudaGetSymbolAddress((void**)&Qb,   g_Qb);
    cudaGetSymbolAddress((void**)&Kb,   g_Kb);
    cudaGetSymbolAddress((void**)&Vb,   g_Vb);
    cudaGetSymbolAddress((void**)&Ctx,  g_Ctx);
    cudaGetSymbolAddress((void**)&Out1, g_Out1);
    cudaGetSymbolAddress((void**)&Ffn,  g_Ffn);
    cudaGetSymbolAddress((void**)&Hc,   g_Hc);
    cudaGetSymbolAddress((void**)&Bias, g_Bias);
    cudaGetSymbolAddress((void**)&WT,   g_WT);

    cudaFuncSetAttribute(tf32_gemm_kernel,
                         cudaFuncAttributeMaxDynamicSharedMemorySize, TFG_SMEM);

    // tf32-rounded weight copies (layouts unchanged: [K,N])
    const int szQ = Ln * Dn * Dn;          // per Q/K/V/O tensor across layers
    const int szF = Ln * Dn * FFNn;
    float* WTq = WT;
    float* WTk = WTq + szQ;
    float* WTv = WTk + szQ;
    float* WTo = WTv + szQ;
    float* WT1 = WTo + szQ;
    float* WT2 = WT1 + szF;
    rna_copy_kernel<<<2048, 256>>>(Wq, WTq, szQ);
    rna_copy_kernel<<<2048, 256>>>(Wk, WTk, szQ);
    rna_copy_kernel<<<2048, 256>>>(Wv, WTv, szQ);
    rna_copy_kernel<<<2048, 256>>>(Wo, WTo, szQ);
    rna_copy_kernel<<<4096, 256>>>(W1, WT1, szF);
    rna_copy_kernel<<<4096, 256>>>(W2, WT2, szF);

    prep_x_kernel<<<ROWSn, 128>>>(sup, cls);
    prep_t_kernel<<<16, 256>>>(qt, st);
    prep_bias_kernel<<<BQn, 64>>>(tfreq, tphase, tw);

    const dim3 gD(Dn / 128, ROWSn / 128);      // N=512  -> 4 x 256
    const dim3 gF(FFNn / 128, ROWSn / 128);    // N=2048 -> 16 x 256

    for (int l = 0; l < Ln; l++) {
        const float* wq = WTq + (size_t)l * Dn * Dn;
        const float* wk = WTk + (size_t)l * Dn * Dn;
        const float* wv = WTv + (size_t)l * Dn * Dn;
        const float* wo = WTo + (size_t)l * Dn * Dn;
        const float* w1 = WT1 + (size_t)l * Dn * FFNn;
        const float* w2 = WT2 + (size_t)l * FFNn * Dn;

        tf32_gemm_kernel<<<gD, 256, TFG_SMEM>>>(X, wq, bq + l * Dn, Qb, Dn, Dn, Dn, 0, 0);
        tf32_gemm_kernel<<<gD, 256, TFG_SMEM>>>(X, wk, bk + l * Dn, Kb, Dn, Dn, Dn, 0, 0);
        tf32_gemm_kernel<<<gD, 256, TFG_SMEM>>>(X, wv, bv + l * Dn, Vb, Dn, Dn, Dn, 0, 0);

        attn_kernel<<<BQn * 4, 128>>>(Bias + (size_t)l * BQn * 64);

        tf32_gemm_kernel<<<gD, 256, TFG_SMEM>>>(Ctx, wo, bo + l * Dn, Qb, Dn, Dn, Dn, 0, 0);
        add_ln_kernel<<<ROWSn, 256>>>(X, Qb, ln1g + l * Dn, ln1b + l * Dn, Out1);

        tf32_gemm_kernel<<<gF, 256, TFG_SMEM>>>(Out1, w1, b1 + l * FFNn, Ffn, FFNn, Dn, Dn, 1, 1);
        tf32_gemm_kernel<<<gD, 256, TFG_SMEM>>>(Ffn, w2, b2 + l * Dn, Qb, Dn, FFNn, FFNn, 0, 0);
        add_ln_kernel<<<ROWSn, 256>>>(Out1, Qb, ln2g + l * Dn, ln2b + l * Dn, X);
    }

    // compress: only s=0 rows feed the output
    sgemm_kernel<<<dim3(1, 32), 256>>>(X, Wc, bc, Hc, BQn, MDn, Dn, Sn * Dn, 0);
    bn_zero_kernel<<<1, 1>>>();
    bn_reduce_kernel<<<256, 256>>>();
    bn_final_kernel<<<2048, 256>>>(bng, bnb, out);

    (void)in_sizes; (void)n_in; (void)out_size;
}

// round 4
// speedup vs baseline: 2.9212x; 1.0312x over previous
#include <cuda_runtime.h>
#include <cuda_bf16.h>
#include <math.h>
#include <stdint.h>

#define BQn   4096
#define Sn    8
#define Dn    512
#define MDn   128
#define Ln    6
#define FFNn  2048
#define TDn   32
#define ROWSn (BQn * Sn)          /* 32768 */
#define SCALE 0.17677669529663687f /* 32^-0.5 */

// ---------------- scratch (device globals; no allocation allowed) -----------
__device__ float g_X   [ROWSn * Dn];
__device__ float g_QKV [ROWSn * 3 * Dn];
__device__ float g_Ctx [ROWSn * Dn];
__device__ float g_Tmp [ROWSn * Dn];
__device__ float g_Out1[ROWSn * Dn];
__device__ float g_Ffn [ROWSn * FFNn];
__device__ float g_Bias[Ln * BQn * 64];
__device__ float g_Tseq[BQn * Sn];
__device__ float g_Hc  [BQn * MDn];
__device__ float g_Stats[2];
__device__ float g_WQKV[Ln * Dn * 3 * Dn];          /* [l][k][3*512] rna   */
__device__ float g_bQKV[Ln * 3 * Dn];
__device__ float g_Wo2 [Ln * Dn * Dn];
__device__ float g_W12 [Ln * Dn * FFNn];
__device__ float g_W22 [Ln * FFNn * Dn];

// ---------------- helpers ----------------------------------------------------
__device__ __forceinline__ float rna_tf32(float x) {
    float r;
    asm("cvt.rna.tf32.f32 %0, %1;" : "=f"(r) : "f"(x));
    return r;
}
__device__ __forceinline__ float gelu_tanh(float v) {
    return 0.5f * v * (1.f + tanhf(0.7978845608028654f * (v + 0.044715f * v * v * v)));
}
__device__ __forceinline__ uint32_t smem_u32(const void* p) {
    uint32_t a;
    asm("{ .reg .u64 t; cvta.to.shared.u64 t, %1; cvt.u32.u64 %0, t; }" : "=r"(a) : "l"(p));
    return a;
}
__device__ __forceinline__ void cp_async16(uint32_t saddr, const void* gaddr) {
    asm volatile("cp.async.ca.shared.global [%0], [%1], 16;" :: "r"(saddr), "l"(gaddr));
}
#define CP_COMMIT() asm volatile("cp.async.commit_group;" ::: "memory")
#define CP_WAIT1()  asm volatile("cp.async.wait_group 1;" ::: "memory")

__device__ __forceinline__ void mma_tf32(float* c, const uint32_t* a, const uint32_t* b) {
    asm volatile(
        "mma.sync.aligned.m16n8k8.row.col.f32.tf32.tf32.f32 "
        "{%0,%1,%2,%3}, {%4,%5,%6,%7}, {%8,%9}, {%0,%1,%2,%3};"
        : "+f"(c[0]), "+f"(c[1]), "+f"(c[2]), "+f"(c[3])
        : "r"(a[0]), "r"(a[1]), "r"(a[2]), "r"(a[3]), "r"(b[0]), "r"(b[1]));
}

// ---------------- tf32 mma.sync GEMM v2 --------------------------------------
// C[M,N] = A[M,K(lda)] @ B[K,N] + bias.  CTA tile 128x256, 8 warps (2x4),
// warp tile 64x64 (4x8 m16n8k8).  2-stage cp.async, K chunks of 32.
// A pad 36 (cf: 4*qr+qc), B pad 264 (cf: 8*qc+qr).
#define AP    36
#define BPW   264
#define A_STG (128 * AP)
#define B_STG (32 * BPW)
#define TFG_SMEM ((2 * A_STG + 2 * B_STG) * 4)

__global__ __launch_bounds__(256, 1)
void tf32_gemm_kernel(const float* __restrict__ A, const float* __restrict__ B,
                      const float* __restrict__ bias, float* __restrict__ C,
                      int N, int K, int lda, int act, int rnd) {
    extern __shared__ float sm[];
    float* AsB = sm;                      // [2][128][AP]
    float* BsB = sm + 2 * A_STG;          // [2][32][BPW]

    const int tid  = threadIdx.x;
    const int lane = tid & 31, warp = tid >> 5;
    const int wm = warp & 1, wn = warp >> 1;
    const int qr = lane >> 2, qc = lane & 3;
    const int rowBase = blockIdx.y * 128;
    const int colBase = blockIdx.x * 256;

    float acc[4][8][4];
#pragma unroll
    for (int i = 0; i < 4; i++)
#pragma unroll
        for (int j = 0; j < 8; j++)
#pragma unroll
            for (int k = 0; k < 4; k++) acc[i][j][k] = 0.f;

    const int nKt = K >> 5;
    uint32_t asmem = smem_u32(AsB);
    uint32_t bsmem = smem_u32(BsB);

    // A: 128x32 floats -> 1024 16B chunks -> 4/thread;  c=tid+i*256: row=c>>3, k4=(c&7)*4
    // B: 32x256 floats -> 2048 16B chunks -> 8/thread;  c=tid+i*256: row=c>>6, n4=(c&63)*4
#define LOAD_TILE(kt, buf) do {                                                   \
    int _k0 = (kt) << 5;                                                          \
    _Pragma("unroll")                                                             \
    for (int _i = 0; _i < 4; _i++) {                                              \
        int _c = tid + _i * 256;                                                  \
        int _r = _c >> 3, _k4 = (_c & 7) << 2;                                    \
        cp_async16(asmem + (((buf) * A_STG + _r * AP + _k4) << 2),                \
                   A + (size_t)(rowBase + _r) * lda + _k0 + _k4);                 \
    }                                                                             \
    _Pragma("unroll")                                                             \
    for (int _i = 0; _i < 8; _i++) {                                              \
        int _c = tid + _i * 256;                                                  \
        int _rb = _c >> 6, _n4 = (_c & 63) << 2;                                  \
        cp_async16(bsmem + (((buf) * B_STG + _rb * BPW + _n4) << 2),              \
                   B + (size_t)(_k0 + _rb) * N + colBase + _n4);                  \
    }                                                                             \
} while (0)

    LOAD_TILE(0, 0);
    CP_COMMIT();

    for (int kt = 0; kt < nKt; kt++) {
        int buf = kt & 1;
        if (kt + 1 < nKt) LOAD_TILE(kt + 1, buf ^ 1);
        CP_COMMIT();
        CP_WAIT1();
        __syncthreads();

        const uint32_t* a = (const uint32_t*)(AsB + buf * A_STG);
        const uint32_t* b = (const uint32_t*)(BsB + buf * B_STG);
#pragma unroll
        for (int ks = 0; ks < 4; ks++) {
            int kk = ks * 8;
            uint32_t af[4][4];
#pragma unroll
            for (int mt = 0; mt < 4; mt++) {
                int rb = wm * 64 + mt * 16;
                af[mt][0] = a[(rb + qr)     * AP + kk + qc];
                af[mt][1] = a[(rb + qr + 8) * AP + kk + qc];
                af[mt][2] = a[(rb + qr)     * AP + kk + qc + 4];
                af[mt][3] = a[(rb + qr + 8) * AP + kk + qc + 4];
            }
            uint32_t bf[8][2];
#pragma unroll
            for (int nt = 0; nt < 8; nt++) {
                int nb = wn * 64 + nt * 8;
                bf[nt][0] = b[(kk + qc)     * BPW + nb + qr];
                bf[nt][1] = b[(kk + qc + 4) * BPW + nb + qr];
            }
#pragma unroll
            for (int mt = 0; mt < 4; mt++)
#pragma unroll
                for (int nt = 0; nt < 8; nt++)
                    mma_tf32(acc[mt][nt], af[mt], bf[nt]);
        }
        __syncthreads();
    }

    // ---- epilogue ----
#pragma unroll
    for (int mt = 0; mt < 4; mt++) {
        int row0 = rowBase + wm * 64 + mt * 16 + qr;
#pragma unroll
        for (int nt = 0; nt < 8; nt++) {
            int col = colBase + wn * 64 + nt * 8 + qc * 2;
            float b0 = bias[col], b1 = bias[col + 1];
            float v0 = acc[mt][nt][0] + b0;
            float v1 = acc[mt][nt][1] + b1;
            float v2 = acc[mt][nt][2] + b0;
            float v3 = acc[mt][nt][3] + b1;
            if (act) { v0 = gelu_tanh(v0); v1 = gelu_tanh(v1); v2 = gelu_tanh(v2); v3 = gelu_tanh(v3); }
            if (rnd) { v0 = rna_tf32(v0); v1 = rna_tf32(v1); v2 = rna_tf32(v2); v3 = rna_tf32(v3); }
            *(float2*)(C + (size_t)row0 * N + col)       = make_float2(v0, v1);
            *(float2*)(C + (size_t)(row0 + 8) * N + col) = make_float2(v2, v3);
        }
    }
#undef LOAD_TILE
}

// ---------------- weight packing --------------------------------------------
__global__ void rna_copy_kernel(const float* __restrict__ src, float* __restrict__ dst, int n) {
    for (int i = blockIdx.x * blockDim.x + threadIdx.x; i < n; i += gridDim.x * blockDim.x)
        dst[i] = rna_tf32(src[i]);
}

// pack Wq|Wk|Wv -> [l][k][1536] with rna; also fused bias
__global__ void pack_qkv_kernel(const float* __restrict__ Wq, const float* __restrict__ Wk,
                                const float* __restrict__ Wv,
                                const float* __restrict__ bq, const float* __restrict__ bk,
                                const float* __restrict__ bv) {
    int n = blockIdx.x * blockDim.x + threadIdx.x;   // over Ln*Dn*Dn
    int total = Ln * Dn * Dn;
    for (; n < total; n += gridDim.x * blockDim.x) {
        int lk = n / Dn, c = n % Dn;                 // lk = l*512 + k
        float q = rna_tf32(Wq[n]);
        float k = rna_tf32(Wk[n]);
        float v = rna_tf32(Wv[n]);
        g_WQKV[(size_t)lk * 1536 + c]        = q;
        g_WQKV[(size_t)lk * 1536 + 512 + c]  = k;
        g_WQKV[(size_t)lk * 1536 + 1024 + c] = v;
    }
    int m = blockIdx.x * blockDim.x + threadIdx.x;
    if (m < Ln * Dn) {
        int l = m / Dn, c = m % Dn;
        g_bQKV[l * 1536 + c]        = bq[m];
        g_bQKV[l * 1536 + 512 + c]  = bk[m];
        g_bQKV[l * 1536 + 1024 + c] = bv[m];
    }
}

// ---------------- prep kernels ----------------------------------------------
__global__ void prep_x_kernel(const float* __restrict__ sup,
                              const float* __restrict__ cls) {
    int row = blockIdx.x;
    int s   = row & 7;
    int bq  = row >> 3;
    int b   = bq >> 5;
    int t   = threadIdx.x;
    float v = (s == 0) ? cls[t] : sup[(b * 7 + (s - 1)) * MDn + t];
    v = rna_tf32(v);
#pragma unroll
    for (int h = 0; h < 4; h++)
        g_X[row * Dn + h * MDn + t] = v;
}

__global__ void prep_t_kernel(const float* __restrict__ query_t,
                              const float* __restrict__ support_t) {
    int bq = blockIdx.x * blockDim.x + threadIdx.x;
    if (bq >= BQn) return;
    int b = bq >> 5, q = bq & 31;
    g_Tseq[bq * 8] = query_t[b * 32 + q];
#pragma unroll
    for (int f = 0; f < 7; f++)
        g_Tseq[bq * 8 + 1 + f] = support_t[b * 7 + f];
}

__global__ void prep_bias_kernel(const float* __restrict__ t_freq,
                                 const float* __restrict__ t_phase,
                                 const float* __restrict__ time_w) {
    int bq  = blockIdx.x;
    int tid = threadIdx.x;             // 64
    __shared__ float tw[Ln][TDn];
    __shared__ float fr[TDn], ph[TDn], ts[Sn];
    if (tid < TDn) { fr[tid] = t_freq[tid]; ph[tid] = t_phase[tid]; }
    if (tid < Sn)  ts[tid] = g_Tseq[bq * 8 + tid];
    for (int i = tid; i < Ln * TDn; i += 64) tw[i / TDn][i % TDn] = time_w[i];
    __syncthreads();
    int s = tid >> 3, t = tid & 7;
    float dt = ts[s] - ts[t];
    float acc[Ln];
#pragma unroll
    for (int l = 0; l < Ln; l++) acc[l] = 0.f;
    for (int td = 0; td < TDn; td++) {
        float c = cosf(dt * fr[td] + ph[td]);
#pragma unroll
        for (int l = 0; l < Ln; l++) acc[l] += c * tw[l][td];
    }
#pragma unroll
    for (int l = 0; l < Ln; l++)
        g_Bias[(l * BQn + bq) * 64 + tid] = acc[l];
}

// ---------------- fp32 SGEMM (used only for the small Wc projection) --------
__global__ __launch_bounds__(256, 2)
void sgemm_kernel(const float* __restrict__ A, const float* __restrict__ W,
                  const float* __restrict__ bias, float* __restrict__ C,
                  int M, int N, int K, int lda, int act) {
    __shared__ float As[8][128];
    __shared__ float Bs[8][128];
    const int tid = threadIdx.x;
    const int rowBase = blockIdx.y * 128;
    const int colBase = blockIdx.x * 128;
    const int ty = tid >> 4, tx = tid & 15;

    const int aRow = tid >> 1;
    const int aK   = (tid & 1) * 4;
    const int bRow = tid >> 5;
    const int bC4  = (tid & 31) * 4;
    const float* Ap = A + (rowBase + aRow) * lda + aK;
    const float* Wp = W + bRow * N + colBase + bC4;

    float acc[8][8];
#pragma unroll
    for (int i = 0; i < 8; i++)
#pragma unroll
        for (int j = 0; j < 8; j++) acc[i][j] = 0.f;

    for (int k0 = 0; k0 < K; k0 += 8) {
        float4 a = *(const float4*)(Ap + k0);
        As[aK + 0][aRow] = a.x;
        As[aK + 1][aRow] = a.y;
        As[aK + 2][aRow] = a.z;
        As[aK + 3][aRow] = a.w;
        *(float4*)&Bs[bRow][bC4] = *(const float4*)(Wp + (size_t)k0 * N);
        __syncthreads();
#pragma unroll
        for (int kk = 0; kk < 8; kk++) {
            float ra[8], rb[8];
#pragma unroll
            for (int i = 0; i < 8; i++) ra[i] = As[kk][ty * 8 + i];
#pragma unroll
            for (int j = 0; j < 4; j++) {
                rb[j]     = Bs[kk][tx * 4 + j];
                rb[j + 4] = Bs[kk][64 + tx * 4 + j];
            }
#pragma unroll
            for (int i = 0; i < 8; i++)
#pragma unroll
                for (int j = 0; j < 8; j++) acc[i][j] = fmaf(ra[i], rb[j], acc[i][j]);
        }
        __syncthreads();
    }
#pragma unroll
    for (int i = 0; i < 8; i++) {
        int row = rowBase + ty * 8 + i;
#pragma unroll
        for (int j = 0; j < 8; j++) {
            int col = colBase + ((j < 4) ? (tx * 4 + j) : (64 + tx * 4 + j - 4));
            float v = acc[i][j] + bias[col];
            if (act) {
                float x3 = v * v * v;
                v = 0.5f * v * (1.f + tanhf(0.7978845608028654f * (v + 0.044715f * x3)));
            }
            C[(size_t)row * N + col] = v;
        }
    }
}

// ---------------- attention on fused QKV buffer ------------------------------
__global__ void attn_kernel(const float* __restrict__ bias) {
    int j   = blockIdx.x;              // 0..BQ*H-1
    int tid = threadIdx.x;             // 128
    __shared__ float qs[8][128], ks[8][128], vs[8][128];
    __shared__ float sc[8][9];
    const float* base = g_QKV + (size_t)(j * 2) * 1536;   // raw reshape: j*1024 floats = 2 rows
#pragma unroll
    for (int s = 0; s < 8; s++) {
        int off = s * 128 + tid;
        int r = off >> 9, c = off & 511;
        const float* rp = base + (size_t)r * 1536 + c;
        qs[s][tid] = rp[0];
        ks[s][tid] = rp[512];
        vs[s][tid] = rp[1024];
    }
    __syncthreads();
    if (tid < 64) {
        int s = tid >> 3, t = tid & 7;
        float d = 0.f;
#pragma unroll
        for (int i = 0; i < 128; i++) d = fmaf(qs[s][i], ks[t][i], d);
        sc[s][t] = d * SCALE + bias[(j & (BQn - 1)) * 64 + tid];
    }
    __syncthreads();
    if (tid < 8) {
        int s = tid;
        float m = sc[s][0];
#pragma unroll
        for (int t = 1; t < 8; t++) m = fmaxf(m, sc[s][t]);
        float sum = 0.f;
#pragma unroll
        for (int t = 0; t < 8; t++) { float e = expf(sc[s][t] - m); sc[s][t] = e; sum += e; }
        float inv = 1.f / sum;
#pragma unroll
        for (int t = 0; t < 8; t++) sc[s][t] *= inv;
    }
    __syncthreads();
    float* cp = g_Ctx + (size_t)j * 1024;
#pragma unroll
    for (int s = 0; s < 8; s++) {
        float a = 0.f;
#pragma unroll
        for (int t = 0; t < 8; t++) a = fmaf(sc[s][t], vs[t][tid], a);
        cp[s * 128 + tid] = rna_tf32(a);
    }
}

// ---------------- residual add + LayerNorm (tf32-rounded output) ------------
__global__ void add_ln_kernel(const float* __restrict__ res, const float* __restrict__ add,
                              const float* __restrict__ g, const float* __restrict__ b,
                              float* __restrict__ out) {
    int row = blockIdx.x;
    int tid = threadIdx.x;             // 256
    float v0 = res[(size_t)row * Dn + tid]       + add[(size_t)row * Dn + tid];
    float v1 = res[(size_t)row * Dn + tid + 256] + add[(size_t)row * Dn + tid + 256];
    float s  = v0 + v1;
    float sq = v0 * v0 + v1 * v1;
#pragma unroll
    for (int o = 16; o > 0; o >>= 1) {
        s  += __shfl_xor_sync(0xffffffffu, s,  o);
        sq += __shfl_xor_sync(0xffffffffu, sq, o);
    }
    __shared__ float rs[8], rq[8];
    __shared__ float s_mean, s_inv;
    int w = tid >> 5;
    if ((tid & 31) == 0) { rs[w] = s; rq[w] = sq; }
    __syncthreads();
    if (tid == 0) {
        float ts = 0.f, tq = 0.f;
#pragma unroll
        for (int i = 0; i < 8; i++) { ts += rs[i]; tq += rq[i]; }
        float mean = ts * (1.f / Dn);
        float var  = tq * (1.f / Dn) - mean * mean;
        s_mean = mean;
        s_inv  = rsqrtf(var + 1e-5f);
    }
    __syncthreads();
    float mean = s_mean, inv = s_inv;
    out[(size_t)row * Dn + tid]       = rna_tf32(g[tid]       * (v0 - mean) * inv + b[tid]);
    out[(size_t)row * Dn + tid + 256] = rna_tf32(g[tid + 256] * (v1 - mean) * inv + b[tid + 256]);
}

// ---------------- final BatchNorm (only s=0 channel needed) -----------------
__global__ void bn_zero_kernel() { g_Stats[0] = 0.f; g_Stats[1] = 0.f; }

__global__ void bn_reduce_kernel() {
    float s = 0.f, q = 0.f;
    for (int i = blockIdx.x * blockDim.x + threadIdx.x; i < BQn * MDn;
         i += gridDim.x * blockDim.x) {
        float v = g_Hc[i]; s += v; q += v * v;
    }
#pragma unroll
    for (int o = 16; o > 0; o >>= 1) {
        s += __shfl_xor_sync(0xffffffffu, s, o);
        q += __shfl_xor_sync(0xffffffffu, q, o);
    }
    __shared__ float rs[8], rq[8];
    int w = threadIdx.x >> 5;
    if ((threadIdx.x & 31) == 0) { rs[w] = s; rq[w] = q; }
    __syncthreads();
    if (threadIdx.x == 0) {
        float ts = 0.f, tq = 0.f;
#pragma unroll
        for (int i = 0; i < 8; i++) { ts += rs[i]; tq += rq[i]; }
        atomicAdd(&g_Stats[0], ts);
        atomicAdd(&g_Stats[1], tq);
    }
}

__global__ void bn_final_kernel(const float* __restrict__ bn_g,
                                const float* __restrict__ bn_b,
                                float* __restrict__ out) {
    const float invN = 1.f / (float)(BQn * MDn);
    float mu  = g_Stats[0] * invN;
    float var = g_Stats[1] * invN - mu * mu;
    float inv = rsqrtf(var + 1e-5f);
    float gg = bn_g[0], bb = bn_b[0];
    for (int i = blockIdx.x * blockDim.x + threadIdx.x; i < BQn * MDn;
         i += gridDim.x * blockDim.x) {
        float h = gg * (g_Hc[i] - mu) * inv + bb;
        out[i] = (h >= 0.f) ? h : 0.01f * h;
    }
}

// ---------------- host orchestration ----------------------------------------
extern "C" void kernel_launch(void* const* d_in, const int* in_sizes, int n_in,
                              void* d_out, int out_size) {
    const float* sup    = (const float*)d_in[0];
    const float* qt     = (const float*)d_in[1];
    const float* st     = (const float*)d_in[2];
    const float* cls    = (const float*)d_in[3];
    const float* tfreq  = (const float*)d_in[4];
    const float* tphase = (const float*)d_in[5];
    const float* Wq = (const float*)d_in[6];
    const float* bq = (const float*)d_in[7];
    const float* Wk = (const float*)d_in[8];
    const float* bk = (const float*)d_in[9];
    const float* Wv = (const float*)d_in[10];
    const float* bv = (const float*)d_in[11];
    const float* Wo = (const float*)d_in[12];
    const float* bo = (const float*)d_in[13];
    const float* ln1g = (const float*)d_in[14];
    const float* ln1b = (const float*)d_in[15];
    const float* tw   = (const float*)d_in[16];
    const float* W1 = (const float*)d_in[17];
    const float* b1 = (const float*)d_in[18];
    const float* W2 = (const float*)d_in[19];
    const float* b2 = (const float*)d_in[20];
    const float* ln2g = (const float*)d_in[21];
    const float* ln2b = (const float*)d_in[22];
    const float* Wc = (const float*)d_in[23];
    const float* bc = (const float*)d_in[24];
    const float* bng = (const float*)d_in[25];
    const float* bnb = (const float*)d_in[26];
    float* out = (float*)d_out;

    float *X, *QKV, *Ctx, *Tmp, *Out1, *Ffn, *Hc, *Bias;
    float *WQKVp, *bQKVp, *Wo2, *W12, *W22;
    cudaGetSymbolAddress((void**)&X,    g_X);
    cudaGetSymbolAddress((void**)&QKV,  g_QKV);
    cudaGetSymbolAddress((void**)&Ctx,  g_Ctx);
    cudaGetSymbolAddress((void**)&Tmp,  g_Tmp);
    cudaGetSymbolAddress((void**)&Out1, g_Out1);
    cudaGetSymbolAddress((void**)&Ffn,  g_Ffn);
    cudaGetSymbolAddress((void**)&Hc,   g_Hc);
    cudaGetSymbolAddress((void**)&Bias, g_Bias);
    cudaGetSymbolAddress((void**)&WQKVp, g_WQKV);
    cudaGetSymbolAddress((void**)&bQKVp, g_bQKV);
    cudaGetSymbolAddress((void**)&Wo2,  g_Wo2);
    cudaGetSymbolAddress((void**)&W12,  g_W12);
    cudaGetSymbolAddress((void**)&W22,  g_W22);

    cudaFuncSetAttribute(tf32_gemm_kernel,
                         cudaFuncAttributeMaxDynamicSharedMemorySize, TFG_SMEM);

    const int szQ = Ln * Dn * Dn;
    const int szF = Ln * Dn * FFNn;
    pack_qkv_kernel<<<2048, 256>>>(Wq, Wk, Wv, bq, bk, bv);
    rna_copy_kernel<<<2048, 256>>>(Wo, Wo2, szQ);
    rna_copy_kernel<<<4096, 256>>>(W1, W12, szF);
    rna_copy_kernel<<<4096, 256>>>(W2, W22, szF);

    prep_x_kernel<<<ROWSn, 128>>>(sup, cls);
    prep_t_kernel<<<16, 256>>>(qt, st);
    prep_bias_kernel<<<BQn, 64>>>(tfreq, tphase, tw);

    const dim3 gQKV(1536 / 256, ROWSn / 128);   // 6 x 256
    const dim3 gD(Dn / 256, ROWSn / 128);       // 2 x 256
    const dim3 gF(FFNn / 256, ROWSn / 128);     // 8 x 256

    for (int l = 0; l < Ln; l++) {
        const float* wqkv = WQKVp + (size_t)l * Dn * 1536;
        const float* bqkv = bQKVp + (size_t)l * 1536;
        const float* wo = Wo2 + (size_t)l * Dn * Dn;
        const float* w1 = W12 + (size_t)l * Dn * FFNn;
        const float* w2 = W22 + (size_t)l * FFNn * Dn;

        tf32_gemm_kernel<<<gQKV, 256, TFG_SMEM>>>(X, wqkv, bqkv, QKV, 1536, Dn, Dn, 0, 0);

        attn_kernel<<<BQn * 4, 128>>>(Bias + (size_t)l * BQn * 64);

        tf32_gemm_kernel<<<gD, 256, TFG_SMEM>>>(Ctx, wo, bo + l * Dn, Tmp, Dn, Dn, Dn, 0, 0);
        add_ln_kernel<<<ROWSn, 256>>>(X, Tmp, ln1g + l * Dn, ln1b + l * Dn, Out1);

        tf32_gemm_kernel<<<gF, 256, TFG_SMEM>>>(Out1, w1, b1 + l * FFNn, Ffn, FFNn, Dn, Dn, 1, 1);
        tf32_gemm_kernel<<<gD, 256, TFG_SMEM>>>(Ffn, w2, b2 + l * Dn, Tmp, Dn, FFNn, FFNn, 0, 0);
        add_ln_kernel<<<ROWSn, 256>>>(Out1, Tmp, ln2g + l * Dn, ln2b + l * Dn, X);
    }

    // compress: only s=0 rows feed the output
    sgemm_kernel<<<dim3(1, 32), 256>>>(X, Wc, bc, Hc, BQn, MDn, Dn, Sn * Dn, 0);
    bn_zero_kernel<<<1, 1>>>();
    bn_reduce_kernel<<<256, 256>>>();
    bn_final_kernel<<<2048, 256>>>(bng, bnb, out);

    (void)in_sizes; (void)n_in; (void)out_size;
}

// round 5
// speedup vs baseline: 4.1203x; 1.4105x over previous
#include <cuda_runtime.h>
#include <cuda_fp16.h>
#include <math.h>
#include <stdint.h>

#define BQn   4096
#define Sn    8
#define Dn    512
#define MDn   128
#define Ln    6
#define FFNn  2048
#define TDn   32
#define ROWSn (BQn * Sn)          /* 32768 */
#define SCALE 0.17677669529663687f /* 32^-0.5 */

// ---------------- scratch (device globals; no allocation allowed) -----------
__device__ float  g_X    [ROWSn * Dn];
__device__ __half g_X16  [ROWSn * Dn];
__device__ float  g_QKV  [ROWSn * 3 * Dn];
__device__ __half g_Ctx16[ROWSn * Dn];
__device__ float  g_Tmp  [ROWSn * Dn];
__device__ float  g_Out1 [ROWSn * Dn];
__device__ __half g_O116 [ROWSn * Dn];
__device__ __half g_Ffn16[ROWSn * FFNn];
__device__ float  g_Bias [Ln * BQn * 64];
__device__ float  g_Tseq [BQn * Sn];
__device__ float  g_Hc   [BQn * MDn];
__device__ float  g_Stats[2];
__device__ __half g_WQKVh[Ln * 1536 * Dn];   /* [l][n(q|k|v)][k] */
__device__ float  g_bQKV [Ln * 1536];
__device__ __half g_Woh  [Ln * Dn * Dn];     /* [l][n][k] */
__device__ __half g_W1h  [Ln * FFNn * Dn];   /* [l][n][k] */
__device__ __half g_W2h  [Ln * Dn * FFNn];   /* [l][n][k] */

// ---------------- helpers ----------------------------------------------------
__device__ __forceinline__ float gelu_tanh(float v) {
    return 0.5f * v * (1.f + tanhf(0.7978845608028654f * (v + 0.044715f * v * v * v)));
}
__device__ __forceinline__ uint32_t smem_u32(const void* p) {
    uint32_t a;
    asm("{ .reg .u64 t; cvta.to.shared.u64 t, %1; cvt.u32.u64 %0, t; }" : "=r"(a) : "l"(p));
    return a;
}
__device__ __forceinline__ void cp_async16(uint32_t saddr, const void* gaddr) {
    asm volatile("cp.async.ca.shared.global [%0], [%1], 16;" :: "r"(saddr), "l"(gaddr));
}
#define CP_COMMIT() asm volatile("cp.async.commit_group;" ::: "memory")
#define CP_WAIT2()  asm volatile("cp.async.wait_group 2;" ::: "memory")

__device__ __forceinline__ void ldmx4(uint32_t& r0, uint32_t& r1, uint32_t& r2, uint32_t& r3,
                                      uint32_t addr) {
    asm volatile("ldmatrix.sync.aligned.m8n8.x4.shared.b16 {%0,%1,%2,%3}, [%4];"
                 : "=r"(r0), "=r"(r1), "=r"(r2), "=r"(r3) : "r"(addr));
}
__device__ __forceinline__ void mma_f16(float* c, const uint32_t* a, const uint32_t* b) {
    asm volatile(
        "mma.sync.aligned.m16n8k16.row.col.f32.f16.f16.f32 "
        "{%0,%1,%2,%3}, {%4,%5,%6,%7}, {%8,%9}, {%0,%1,%2,%3};"
        : "+f"(c[0]), "+f"(c[1]), "+f"(c[2]), "+f"(c[3])
        : "r"(a[0]), "r"(a[1]), "r"(a[2]), "r"(a[3]), "r"(b[0]), "r"(b[1]));
}

// ---------------- fp16 mma.sync GEMM -----------------------------------------
// C[M,N] = A[M,K(lda)] @ Bt[N,K]^T + bias.  CTA 128x256, 8 warps (2x4),
// warp tile 64x64 (4x8 m16n8k16).  3-stage cp.async, K chunks of 32 halves.
// Smem rows padded to 40 halves (80B) -> conflict-free ldmatrix.
#define APh    40
#define BPh    40
#define A_BYT  (128 * APh * 2)      /* 10240 */
#define B_BYT  (256 * BPh * 2)      /* 20480 */
#define STG_BYT (A_BYT + B_BYT)     /* 30720 */
#define HG_SMEM (3 * STG_BYT)       /* 92160 */

__global__ __launch_bounds__(256, 1)
void hgemm_kernel(const __half* __restrict__ A, const __half* __restrict__ Bt,
                  const float* __restrict__ bias, float* __restrict__ Cf,
                  __half* __restrict__ Ch,
                  int N, int K, int lda, int act) {
    extern __shared__ char smraw[];
    uint32_t sb = smem_u32(smraw);

    const int tid  = threadIdx.x;
    const int lane = tid & 31, warp = tid >> 5;
    const int wm = warp & 1, wn = warp >> 1;
    const int qr = lane >> 2, qc = lane & 3;
    const int jj = lane >> 3, rr = lane & 7;      // ldmatrix lane mapping
    const int rowBase = blockIdx.y * 128;
    const int colBase = blockIdx.x * 256;

    float acc[4][8][4];
#pragma unroll
    for (int i = 0; i < 4; i++)
#pragma unroll
        for (int j = 0; j < 8; j++)
#pragma unroll
            for (int k = 0; k < 4; k++) acc[i][j][k] = 0.f;

    const int nKt = K >> 5;

    // ldmatrix base offsets (within a stage)
    // A frag (mt, kc): row = wm*64+mt*16+(jj&1)*8+rr, kbase = kc*16+(jj>>1)*8
    uint32_t a_off[4], b_off[4];
#pragma unroll
    for (int mt = 0; mt < 4; mt++)
        a_off[mt] = ((wm * 64 + mt * 16 + (jj & 1) * 8 + rr) * APh + (jj >> 1) * 8) * 2;
#pragma unroll
    for (int p = 0; p < 4; p++)
        b_off[p] = (uint32_t)(A_BYT) +
                   ((wn * 64 + p * 16 + (jj & 1) * 8 + rr) * BPh + (jj >> 1) * 8) * 2;

#define LOAD_TILE(kt, stg) do {                                                   \
    int _k0 = (kt) << 5;                                                          \
    uint32_t _sb = sb + (stg) * STG_BYT;                                          \
    _Pragma("unroll")                                                             \
    for (int _i = 0; _i < 2; _i++) {                                              \
        int _c = tid + _i * 256;                                                  \
        int _r = _c >> 2, _k8 = (_c & 3) << 3;                                    \
        cp_async16(_sb + (_r * APh + _k8) * 2,                                    \
                   A + (size_t)(rowBase + _r) * lda + _k0 + _k8);                 \
    }                                                                             \
    _Pragma("unroll")                                                             \
    for (int _i = 0; _i < 4; _i++) {                                              \
        int _c = tid + _i * 256;                                                  \
        int _n = _c >> 2, _k8 = (_c & 3) << 3;                                    \
        cp_async16(_sb + A_BYT + (_n * BPh + _k8) * 2,                            \
                   Bt + (size_t)(colBase + _n) * K + _k0 + _k8);                  \
    }                                                                             \
} while (0)

    LOAD_TILE(0, 0); CP_COMMIT();
    LOAD_TILE(1, 1); CP_COMMIT();

    for (int kt = 0; kt < nKt; kt++) {
        int stg = kt % 3;
        if (kt + 2 < nKt) LOAD_TILE(kt + 2, (kt + 2) % 3);
        CP_COMMIT();
        CP_WAIT2();
        __syncthreads();

        uint32_t stage = sb + stg * STG_BYT;
#pragma unroll
        for (int kc = 0; kc < 2; kc++) {
            uint32_t kadd = kc * 32;   // 16 halves
            uint32_t af[4][4];
#pragma unroll
            for (int mt = 0; mt < 4; mt++)
                ldmx4(af[mt][0], af[mt][1], af[mt][2], af[mt][3], stage + a_off[mt] + kadd);
            uint32_t bf[8][2];
#pragma unroll
            for (int p = 0; p < 4; p++) {
                uint32_t r0, r1, r2, r3;
                ldmx4(r0, r1, r2, r3, stage + b_off[p] + kadd);
                bf[2 * p][0] = r0; bf[2 * p + 1][0] = r1;
                bf[2 * p][1] = r2; bf[2 * p + 1][1] = r3;
            }
#pragma unroll
            for (int mt = 0; mt < 4; mt++)
#pragma unroll
                for (int nt = 0; nt < 8; nt++)
                    mma_f16(acc[mt][nt], af[mt], bf[nt]);
        }
        __syncthreads();
    }

    // ---- epilogue ----
#pragma unroll
    for (int mt = 0; mt < 4; mt++) {
        int row0 = rowBase + wm * 64 + mt * 16 + qr;
#pragma unroll
        for (int nt = 0; nt < 8; nt++) {
            int col = colBase + wn * 64 + nt * 8 + qc * 2;
            float b0 = bias[col], b1 = bias[col + 1];
            float v0 = acc[mt][nt][0] + b0;
            float v1 = acc[mt][nt][1] + b1;
            float v2 = acc[mt][nt][2] + b0;
            float v3 = acc[mt][nt][3] + b1;
            if (act) { v0 = gelu_tanh(v0); v1 = gelu_tanh(v1); v2 = gelu_tanh(v2); v3 = gelu_tanh(v3); }
            if (Cf) {
                *(float2*)(Cf + (size_t)row0 * N + col)       = make_float2(v0, v1);
                *(float2*)(Cf + (size_t)(row0 + 8) * N + col) = make_float2(v2, v3);
            }
            if (Ch) {
                *(__half2*)(Ch + (size_t)row0 * N + col)       = __floats2half2_rn(v0, v1);
                *(__half2*)(Ch + (size_t)(row0 + 8) * N + col) = __floats2half2_rn(v2, v3);
            }
        }
    }
#undef LOAD_TILE
}

// ---------------- weight packing: transpose [K][N] f32 -> [N][K] half --------
// One launch covers all 6 weight groups x 6 layers.
// per-layer tile counts: Q 256, K 256, V 256, O 256, W1 1024, W2 1024 = 3072
__global__ void pack_weights_kernel(const float* __restrict__ Wq, const float* __restrict__ Wk,
                                    const float* __restrict__ Wv, const float* __restrict__ Wo,
                                    const float* __restrict__ W1, const float* __restrict__ W2) {
    __shared__ float t[32][33];
    int bid = blockIdx.x;
    int l = bid / 3072, tt = bid % 3072;
    const float* src; __half* dst; int Kd, Nd, tk, tn;
    if (tt < 768) {
        int which = tt / 256, r = tt % 256;
        src = (which == 0 ? Wq : which == 1 ? Wk : Wv) + (size_t)l * Dn * Dn;
        dst = g_WQKVh + (size_t)l * 1536 * Dn + (size_t)which * Dn * Dn;
        Kd = Dn; Nd = Dn; tk = r & 15; tn = r >> 4;
    } else if (tt < 1024) {
        int r = tt - 768;
        src = Wo + (size_t)l * Dn * Dn;
        dst = g_Woh + (size_t)l * Dn * Dn;
        Kd = Dn; Nd = Dn; tk = r & 15; tn = r >> 4;
    } else if (tt < 2048) {
        int r = tt - 1024;
        src = W1 + (size_t)l * Dn * FFNn;
        dst = g_W1h + (size_t)l * FFNn * Dn;
        Kd = Dn; Nd = FFNn; tk = r & 15; tn = r >> 4;
    } else {
        int r = tt - 2048;
        src = W2 + (size_t)l * FFNn * Dn;
        dst = g_W2h + (size_t)l * Dn * FFNn;
        Kd = FFNn; Nd = Dn; tk = r & 63; tn = r >> 6;
    }
    int k0 = tk * 32, n0 = tn * 32;
    int x = threadIdx.x, y = threadIdx.y;
#pragma unroll
    for (int i = 0; i < 32; i += 8)
        t[y + i][x] = src[(size_t)(k0 + y + i) * Nd + n0 + x];
    __syncthreads();
#pragma unroll
    for (int i = 0; i < 32; i += 8)
        dst[(size_t)(n0 + y + i) * Kd + k0 + x] = __float2half(t[x][y + i]);
}

__global__ void pack_bias_kernel(const float* __restrict__ bq, const float* __restrict__ bk,
                                 const float* __restrict__ bv) {
    int m = blockIdx.x * blockDim.x + threadIdx.x;
    if (m < Ln * Dn) {
        int l = m / Dn, c = m % Dn;
        g_bQKV[l * 1536 + c]        = bq[m];
        g_bQKV[l * 1536 + 512 + c]  = bk[m];
        g_bQKV[l * 1536 + 1024 + c] = bv[m];
    }
}

// ---------------- prep kernels ----------------------------------------------
__global__ void prep_x_kernel(const float* __restrict__ sup,
                              const float* __restrict__ cls) {
    int row = blockIdx.x;
    int s   = row & 7;
    int bq  = row >> 3;
    int b   = bq >> 5;
    int t   = threadIdx.x;
    float v = (s == 0) ? cls[t] : sup[(b * 7 + (s - 1)) * MDn + t];
    __half h = __float2half(v);
#pragma unroll
    for (int hh = 0; hh < 4; hh++) {
        g_X  [row * Dn + hh * MDn + t] = v;
        g_X16[row * Dn + hh * MDn + t] = h;
    }
}

__global__ void prep_t_kernel(const float* __restrict__ query_t,
                              const float* __restrict__ support_t) {
    int bq = blockIdx.x * blockDim.x + threadIdx.x;
    if (bq >= BQn) return;
    int b = bq >> 5, q = bq & 31;
    g_Tseq[bq * 8] = query_t[b * 32 + q];
#pragma unroll
    for (int f = 0; f < 7; f++)
        g_Tseq[bq * 8 + 1 + f] = support_t[b * 7 + f];
}

__global__ void prep_bias_kernel(const float* __restrict__ t_freq,
                                 const float* __restrict__ t_phase,
                                 const float* __restrict__ time_w) {
    int bq  = blockIdx.x;
    int tid = threadIdx.x;             // 64
    __shared__ float tw[Ln][TDn];
    __shared__ float fr[TDn], ph[TDn], ts[Sn];
    if (tid < TDn) { fr[tid] = t_freq[tid]; ph[tid] = t_phase[tid]; }
    if (tid < Sn)  ts[tid] = g_Tseq[bq * 8 + tid];
    for (int i = tid; i < Ln * TDn; i += 64) tw[i / TDn][i % TDn] = time_w[i];
    __syncthreads();
    int s = tid >> 3, t = tid & 7;
    float dt = ts[s] - ts[t];
    float acc[Ln];
#pragma unroll
    for (int l = 0; l < Ln; l++) acc[l] = 0.f;
    for (int td = 0; td < TDn; td++) {
        float c = cosf(dt * fr[td] + ph[td]);
#pragma unroll
        for (int l = 0; l < Ln; l++) acc[l] += c * tw[l][td];
    }
#pragma unroll
    for (int l = 0; l < Ln; l++)
        g_Bias[(l * BQn + bq) * 64 + tid] = acc[l];
}

// ---------------- fp32 SGEMM (small Wc projection only) ---------------------
__global__ __launch_bounds__(256, 2)
void sgemm_kernel(const float* __restrict__ A, const float* __restrict__ W,
                  const float* __restrict__ bias, float* __restrict__ C,
                  int M, int N, int K, int lda, int act) {
    __shared__ float As[8][128];
    __shared__ float Bs[8][128];
    const int tid = threadIdx.x;
    const int rowBase = blockIdx.y * 128;
    const int colBase = blockIdx.x * 128;
    const int ty = tid >> 4, tx = tid & 15;

    const int aRow = tid >> 1;
    const int aK   = (tid & 1) * 4;
    const int bRow = tid >> 5;
    const int bC4  = (tid & 31) * 4;
    const float* Ap = A + (rowBase + aRow) * lda + aK;
    const float* Wp = W + bRow * N + colBase + bC4;

    float acc[8][8];
#pragma unroll
    for (int i = 0; i < 8; i++)
#pragma unroll
        for (int j = 0; j < 8; j++) acc[i][j] = 0.f;

    for (int k0 = 0; k0 < K; k0 += 8) {
        float4 a = *(const float4*)(Ap + k0);
        As[aK + 0][aRow] = a.x;
        As[aK + 1][aRow] = a.y;
        As[aK + 2][aRow] = a.z;
        As[aK + 3][aRow] = a.w;
        *(float4*)&Bs[bRow][bC4] = *(const float4*)(Wp + (size_t)k0 * N);
        __syncthreads();
#pragma unroll
        for (int kk = 0; kk < 8; kk++) {
            float ra[8], rb[8];
#pragma unroll
            for (int i = 0; i < 8; i++) ra[i] = As[kk][ty * 8 + i];
#pragma unroll
            for (int j = 0; j < 4; j++) {
                rb[j]     = Bs[kk][tx * 4 + j];
                rb[j + 4] = Bs[kk][64 + tx * 4 + j];
            }
#pragma unroll
            for (int i = 0; i < 8; i++)
#pragma unroll
                for (int j = 0; j < 8; j++) acc[i][j] = fmaf(ra[i], rb[j], acc[i][j]);
        }
        __syncthreads();
    }
#pragma unroll
    for (int i = 0; i < 8; i++) {
        int row = rowBase + ty * 8 + i;
#pragma unroll
        for (int j = 0; j < 8; j++) {
            int col = colBase + ((j < 4) ? (tx * 4 + j) : (64 + tx * 4 + j - 4));
            float v = acc[i][j] + bias[col];
            if (act) {
                float x3 = v * v * v;
                v = 0.5f * v * (1.f + tanhf(0.7978845608028654f * (v + 0.044715f * x3)));
            }
            C[(size_t)row * N + col] = v;
        }
    }
}

// ---------------- attention on fused QKV buffer ------------------------------
__global__ void attn_kernel(const float* __restrict__ bias) {
    int j   = blockIdx.x;              // 0..BQ*H-1
    int tid = threadIdx.x;             // 128
    __shared__ float qs[8][128], ks[8][128], vs[8][128];
    __shared__ float sc[8][9];
    const float* base = g_QKV + (size_t)(j * 2) * 1536;   // raw reshape: j*1024 floats = 2 rows
#pragma unroll
    for (int s = 0; s < 8; s++) {
        int off = s * 128 + tid;
        int r = off >> 9, c = off & 511;
        const float* rp = base + (size_t)r * 1536 + c;
        qs[s][tid] = rp[0];
        ks[s][tid] = rp[512];
        vs[s][tid] = rp[1024];
    }
    __syncthreads();
    if (tid < 64) {
        int s = tid >> 3, t = tid & 7;
        float d = 0.f;
#pragma unroll
        for (int i = 0; i < 128; i++) d = fmaf(qs[s][i], ks[t][i], d);
        sc[s][t] = d * SCALE + bias[(j & (BQn - 1)) * 64 + tid];
    }
    __syncthreads();
    if (tid < 8) {
        int s = tid;
        float m = sc[s][0];
#pragma unroll
        for (int t = 1; t < 8; t++) m = fmaxf(m, sc[s][t]);
        float sum = 0.f;
#pragma unroll
        for (int t = 0; t < 8; t++) { float e = expf(sc[s][t] - m); sc[s][t] = e; sum += e; }
        float inv = 1.f / sum;
#pragma unroll
        for (int t = 0; t < 8; t++) sc[s][t] *= inv;
    }
    __syncthreads();
    __half* cp = g_Ctx16 + (size_t)j * 1024;
#pragma unroll
    for (int s = 0; s < 8; s++) {
        float a = 0.f;
#pragma unroll
        for (int t = 0; t < 8; t++) a = fmaf(sc[s][t], vs[t][tid], a);
        cp[s * 128 + tid] = __float2half(a);
    }
}

// ---------------- residual add + LayerNorm (fp32 + half outputs) ------------
__global__ void add_ln_kernel(const float* __restrict__ res, const float* __restrict__ add,
                              const float* __restrict__ g, const float* __restrict__ b,
                              float* __restrict__ out, __half* __restrict__ out16) {
    int row = blockIdx.x;
    int tid = threadIdx.x;             // 256
    float v0 = res[(size_t)row * Dn + tid]       + add[(size_t)row * Dn + tid];
    float v1 = res[(size_t)row * Dn + tid + 256] + add[(size_t)row * Dn + tid + 256];
    float s  = v0 + v1;
    float sq = v0 * v0 + v1 * v1;
#pragma unroll
    for (int o = 16; o > 0; o >>= 1) {
        s  += __shfl_xor_sync(0xffffffffu, s,  o);
        sq += __shfl_xor_sync(0xffffffffu, sq, o);
    }
    __shared__ float rs[8], rq[8];
    __shared__ float s_mean, s_inv;
    int w = tid >> 5;
    if ((tid & 31) == 0) { rs[w] = s; rq[w] = sq; }
    __syncthreads();
    if (tid == 0) {
        float ts = 0.f, tq = 0.f;
#pragma unroll
        for (int i = 0; i < 8; i++) { ts += rs[i]; tq += rq[i]; }
        float mean = ts * (1.f / Dn);
        float var  = tq * (1.f / Dn) - mean * mean;
        s_mean = mean;
        s_inv  = rsqrtf(var + 1e-5f);
    }
    __syncthreads();
    float mean = s_mean, inv = s_inv;
    float o0 = g[tid]       * (v0 - mean) * inv + b[tid];
    float o1 = g[tid + 256] * (v1 - mean) * inv + b[tid + 256];
    out[(size_t)row * Dn + tid]         = o0;
    out[(size_t)row * Dn + tid + 256]   = o1;
    out16[(size_t)row * Dn + tid]       = __float2half(o0);
    out16[(size_t)row * Dn + tid + 256] = __float2half(o1);
}

// ---------------- final BatchNorm (only s=0 channel needed) -----------------
__global__ void bn_zero_kernel() { g_Stats[0] = 0.f; g_Stats[1] = 0.f; }

__global__ void bn_reduce_kernel() {
    float s = 0.f, q = 0.f;
    for (int i = blockIdx.x * blockDim.x + threadIdx.x; i < BQn * MDn;
         i += gridDim.x * blockDim.x) {
        float v = g_Hc[i]; s += v; q += v * v;
    }
#pragma unroll
    for (int o = 16; o > 0; o >>= 1) {
        s += __shfl_xor_sync(0xffffffffu, s, o);
        q += __shfl_xor_sync(0xffffffffu, q, o);
    }
    __shared__ float rs[8], rq[8];
    int w = threadIdx.x >> 5;
    if ((threadIdx.x & 31) == 0) { rs[w] = s; rq[w] = q; }
    __syncthreads();
    if (threadIdx.x == 0) {
        float ts = 0.f, tq = 0.f;
#pragma unroll
        for (int i = 0; i < 8; i++) { ts += rs[i]; tq += rq[i]; }
        atomicAdd(&g_Stats[0], ts);
        atomicAdd(&g_Stats[1], tq);
    }
}

__global__ void bn_final_kernel(const float* __restrict__ bn_g,
                                const float* __restrict__ bn_b,
                                float* __restrict__ out) {
    const float invN = 1.f / (float)(BQn * MDn);
    float mu  = g_Stats[0] * invN;
    float var = g_Stats[1] * invN - mu * mu;
    float inv = rsqrtf(var + 1e-5f);
    float gg = bn_g[0], bb = bn_b[0];
    for (int i = blockIdx.x * blockDim.x + threadIdx.x; i < BQn * MDn;
         i += gridDim.x * blockDim.x) {
        float h = gg * (g_Hc[i] - mu) * inv + bb;
        out[i] = (h >= 0.f) ? h : 0.01f * h;
    }
}

// ---------------- host orchestration ----------------------------------------
extern "C" void kernel_launch(void* const* d_in, const int* in_sizes, int n_in,
                              void* d_out, int out_size) {
    const float* sup    = (const float*)d_in[0];
    const float* qt     = (const float*)d_in[1];
    const float* st     = (const float*)d_in[2];
    const float* cls    = (const float*)d_in[3];
    const float* tfreq  = (const float*)d_in[4];
    const float* tphase = (const float*)d_in[5];
    const float* Wq = (const float*)d_in[6];
    const float* bq = (const float*)d_in[7];
    const float* Wk = (const float*)d_in[8];
    const float* bk = (const float*)d_in[9];
    const float* Wv = (const float*)d_in[10];
    const float* bv = (const float*)d_in[11];
    const float* Wo = (const float*)d_in[12];
    const float* bo = (const float*)d_in[13];
    const float* ln1g = (const float*)d_in[14];
    const float* ln1b = (const float*)d_in[15];
    const float* tw   = (const float*)d_in[16];
    const float* W1 = (const float*)d_in[17];
    const float* b1 = (const float*)d_in[18];
    const float* W2 = (const float*)d_in[19];
    const float* b2 = (const float*)d_in[20];
    const float* ln2g = (const float*)d_in[21];
    const float* ln2b = (const float*)d_in[22];
    const float* Wc = (const float*)d_in[23];
    const float* bc = (const float*)d_in[24];
    const float* bng = (const float*)d_in[25];
    const float* bnb = (const float*)d_in[26];
    float* out = (float*)d_out;

    float *X, *QKV, *Tmp, *Out1, *Hc, *Bias, *bQKVp;
    __half *X16, *Ctx16, *O116, *Ffn16, *WQKVh, *Woh, *W1h, *W2h;
    cudaGetSymbolAddress((void**)&X,     g_X);
    cudaGetSymbolAddress((void**)&X16,   g_X16);
    cudaGetSymbolAddress((void**)&QKV,   g_QKV);
    cudaGetSymbolAddress((void**)&Ctx16, g_Ctx16);
    cudaGetSymbolAddress((void**)&Tmp,   g_Tmp);
    cudaGetSymbolAddress((void**)&Out1,  g_Out1);
    cudaGetSymbolAddress((void**)&O116,  g_O116);
    cudaGetSymbolAddress((void**)&Ffn16, g_Ffn16);
    cudaGetSymbolAddress((void**)&Hc,    g_Hc);
    cudaGetSymbolAddress((void**)&Bias,  g_Bias);
    cudaGetSymbolAddress((void**)&bQKVp, g_bQKV);
    cudaGetSymbolAddress((void**)&WQKVh, g_WQKVh);
    cudaGetSymbolAddress((void**)&Woh,   g_Woh);
    cudaGetSymbolAddress((void**)&W1h,   g_W1h);
    cudaGetSymbolAddress((void**)&W2h,   g_W2h);

    cudaFuncSetAttribute(hgemm_kernel,
                         cudaFuncAttributeMaxDynamicSharedMemorySize, HG_SMEM);

    // launches 1..5 (so ncu -s 5 captures the first hgemm)
    pack_weights_kernel<<<Ln * 3072, dim3(32, 8)>>>(Wq, Wk, Wv, Wo, W1, W2);
    pack_bias_kernel<<<12, 256>>>(bq, bk, bv);
    prep_x_kernel<<<ROWSn, 128>>>(sup, cls);
    prep_t_kernel<<<16, 256>>>(qt, st);
    prep_bias_kernel<<<BQn, 64>>>(tfreq, tphase, tw);

    const dim3 gQKV(1536 / 256, ROWSn / 128);   // 6 x 256
    const dim3 gD(Dn / 256, ROWSn / 128);       // 2 x 256
    const dim3 gF(FFNn / 256, ROWSn / 128);     // 8 x 256

    for (int l = 0; l < Ln; l++) {
        const __half* wqkv = WQKVh + (size_t)l * 1536 * Dn;
        const float*  bqkv = bQKVp + (size_t)l * 1536;
        const __half* wo = Woh + (size_t)l * Dn * Dn;
        const __half* w1 = W1h + (size_t)l * FFNn * Dn;
        const __half* w2 = W2h + (size_t)l * Dn * FFNn;

        hgemm_kernel<<<gQKV, 256, HG_SMEM>>>(X16, wqkv, bqkv, QKV, nullptr, 1536, Dn, Dn, 0);

        attn_kernel<<<BQn * 4, 128>>>(Bias + (size_t)l * BQn * 64);

        hgemm_kernel<<<gD, 256, HG_SMEM>>>(Ctx16, wo, bo + l * Dn, Tmp, nullptr, Dn, Dn, Dn, 0);
        add_ln_kernel<<<ROWSn, 256>>>(X, Tmp, ln1g + l * Dn, ln1b + l * Dn, Out1, O116);

        hgemm_kernel<<<gF, 256, HG_SMEM>>>(O116, w1, b1 + l * FFNn, nullptr, Ffn16, FFNn, Dn, Dn, 1);
        hgemm_kernel<<<gD, 256, HG_SMEM>>>(Ffn16, w2, b2 + l * Dn, Tmp, nullptr, Dn, FFNn, FFNn, 0);
        add_ln_kernel<<<ROWSn, 256>>>(Out1, Tmp, ln2g + l * Dn, ln2b + l * Dn, X, X16);
    }

    // compress: only s=0 rows feed the output (exact fp32 path)
    sgemm_kernel<<<dim3(1, 32), 256>>>(X, Wc, bc, Hc, BQn, MDn, Dn, Sn * Dn, 0);
    bn_zero_kernel<<<1, 1>>>();
    bn_reduce_kernel<<<256, 256>>>();
    bn_final_kernel<<<2048, 256>>>(bng, bnb, out);

    (void)in_sizes; (void)n_in; (void)out_size;
}

// round 7
// speedup vs baseline: 4.8312x; 1.1725x over previous
#include <cuda_runtime.h>
#include <cuda.h>
#include <cuda_fp16.h>
#include <math.h>
#include <stdint.h>

#define BQn   4096
#define Sn    8
#define Dn    512
#define MDn   128
#define Ln    6
#define FFNn  2048
#define TDn   32
#define ROWSn (BQn * Sn)          /* 32768 */
#define SCALE 0.17677669529663687f /* 32^-0.5 */

// ---------------- scratch (device globals; no allocation allowed) -----------
// All TMA-visible buffers are 1024B-aligned (TMA/global + SW128 contract).
__device__ float  g_X    [ROWSn * Dn];
__device__ __align__(1024) __half g_X16  [ROWSn * Dn];
__device__ float  g_QKV  [ROWSn * 3 * Dn];
__device__ __align__(1024) __half g_Ctx16[ROWSn * Dn];
__device__ float  g_Tmp  [ROWSn * Dn];
__device__ float  g_Out1 [ROWSn * Dn];
__device__ __align__(1024) __half g_O116 [ROWSn * Dn];
__device__ __align__(1024) __half g_Ffn16[ROWSn * FFNn];
__device__ float  g_Bias [Ln * BQn * 64];
__device__ float  g_Tseq [BQn * Sn];
__device__ float  g_Hc   [BQn * MDn];
__device__ float  g_Stats[2];
__device__ __align__(1024) __half g_WQKVh[Ln * 1536 * Dn];   /* [l][n(q|k|v)][k] */
__device__ float  g_bQKV [Ln * 1536];
__device__ __align__(1024) __half g_Woh  [Ln * Dn * Dn];     /* [l][n][k] */
__device__ __align__(1024) __half g_W1h  [Ln * FFNn * Dn];   /* [l][n][k] */
__device__ __align__(1024) __half g_W2h  [Ln * Dn * FFNn];   /* [l][n][k] */

// ---------------- helpers ----------------------------------------------------
__device__ __forceinline__ float gelu_tanh(float v) {
    return 0.5f * v * (1.f + tanhf(0.7978845608028654f * (v + 0.044715f * v * v * v)));
}
__device__ __forceinline__ uint32_t smem_u32(const void* p) {
    uint32_t a;
    asm("{ .reg .u64 t; cvta.to.shared.u64 t, %1; cvt.u32.u64 %0, t; }" : "=r"(a) : "l"(p));
    return a;
}

#define MBAR_INIT(addr, cnt) \
    asm volatile("mbarrier.init.shared.b64 [%0], %1;" :: "r"(addr), "r"((uint32_t)(cnt)) : "memory")
#define MBAR_EXPECT_TX(addr, bytes) \
    asm volatile("mbarrier.arrive.expect_tx.shared.b64 _, [%0], %1;" :: "r"(addr), "r"((uint32_t)(bytes)) : "memory")
#define MBAR_WAIT(addr, parity) do {                                                   \
    uint32_t _m = (addr); uint32_t _p = (parity); uint32_t _d;                         \
    asm volatile("{\n\t.reg .pred p;\n\t"                                              \
        "mbarrier.try_wait.parity.acquire.cta.shared::cta.b64 p, [%1], %2;\n\t"        \
        "selp.b32 %0, 1, 0, p;\n\t}" : "=r"(_d) : "r"(_m), "r"(_p) : "memory");        \
    if (!_d) {                                                                         \
        asm volatile("{\n\t.reg .pred P1;\n\t"                                         \
            "W_%=:\n\t"                                                                \
            "mbarrier.try_wait.parity.acquire.cta.shared::cta.b64 P1, [%0], %1, 0x989680;\n\t" \
            "@P1 bra.uni D_%=;\n\t"                                                    \
            "bra.uni W_%=;\n\t"                                                        \
            "D_%=:\n\t}" :: "r"(_m), "r"(_p) : "memory");                              \
    }                                                                                  \
} while (0)

#define TMA_LOAD_3D(smem, map, x, y, z, mbar)                                             \
    asm volatile("cp.async.bulk.tensor.3d.shared::cta.global.tile.mbarrier::complete_tx::bytes " \
                 "[%0], [%1, {%2, %3, %4}], [%5];"                                        \
                 :: "r"((uint32_t)(smem)), "l"(map), "r"((int)(x)), "r"((int)(y)),        \
                    "r"((int)(z)), "r"((uint32_t)(mbar)) : "memory")

__device__ __forceinline__ void ldmx4(uint32_t& r0, uint32_t& r1, uint32_t& r2, uint32_t& r3,
                                      uint32_t addr) {
    asm volatile("ldmatrix.sync.aligned.m8n8.x4.shared.b16 {%0,%1,%2,%3}, [%4];"
                 : "=r"(r0), "=r"(r1), "=r"(r2), "=r"(r3) : "r"(addr));
}
__device__ __forceinline__ void mma_f16(float* c, const uint32_t* a, const uint32_t* b) {
    asm volatile(
        "mma.sync.aligned.m16n8k16.row.col.f32.f16.f16.f32 "
        "{%0,%1,%2,%3}, {%4,%5,%6,%7}, {%8,%9}, {%0,%1,%2,%3};"
        : "+f"(c[0]), "+f"(c[1]), "+f"(c[2]), "+f"(c[3])
        : "r"(a[0]), "r"(a[1]), "r"(a[2]), "r"(a[3]), "r"(b[0]), "r"(b[1]));
}

// ---------------- fp16 TMA + mma.sync GEMM -----------------------------------
// C[M,N] = A[M,K] @ Bt[N,K]^T + bias.  CTA 128x256, 8 warps (2x4),
// warp tile 64x64.  K chunks of 64 halves (128B rows, SW128), 3-stage TMA.
// stage layout: A[128][128B] at +0 (16KB), B[256][128B] at +16384 (32KB)
#define STG_BYT  49152
#define HG_SMEM  (3 * STG_BYT + 1024)   /* +1KB so we can align sb to 1024 */

__global__ __launch_bounds__(256, 1)
void hgemm_kernel(const __grid_constant__ CUtensorMap tmA,
                  const __grid_constant__ CUtensorMap tmB,
                  const float* __restrict__ bias, float* __restrict__ Cf,
                  __half* __restrict__ Ch,
                  int N, int nKt, int layer, int act) {
    extern __shared__ char smraw[];
    __shared__ __align__(8) uint64_t mbar[3];
    uint32_t sb = (smem_u32(smraw) + 1023u) & ~1023u;   // 1024B-aligned stage base
    uint32_t mb0 = smem_u32(&mbar[0]);

    const int tid  = threadIdx.x;
    const int lane = tid & 31, warp = tid >> 5;
    const int wm = warp & 1, wn = warp >> 1;
    const int qr = lane >> 2, qc = lane & 3;
    const int jj = lane >> 3, rr = lane & 7;
    const int rowBase = blockIdx.y * 128;
    const int colBase = blockIdx.x * 256;

    if (tid == 0) {
        MBAR_INIT(mb0 + 0,  1);
        MBAR_INIT(mb0 + 8,  1);
        MBAR_INIT(mb0 + 16, 1);
    }
    __syncthreads();

    if (tid == 0) {
        int pre = nKt < 3 ? nKt : 3;
        for (int s = 0; s < pre; s++) {
            MBAR_EXPECT_TX(mb0 + s * 8, STG_BYT);
            TMA_LOAD_3D(sb + s * STG_BYT,         &tmA, s * 64, rowBase, 0,     mb0 + s * 8);
            TMA_LOAD_3D(sb + s * STG_BYT + 16384, &tmB, s * 64, colBase, layer, mb0 + s * 8);
        }
    }

    float acc[4][8][4];
#pragma unroll
    for (int i = 0; i < 4; i++)
#pragma unroll
        for (int j = 0; j < 8; j++)
#pragma unroll
            for (int k = 0; k < 4; k++) acc[i][j][k] = 0.f;

    // ldmatrix swizzled addressing: addr = base + row*128 + (colb ^ (rr<<4))
    const uint32_t xorv = (uint32_t)rr << 4;
    uint32_t a_row[4], b_row[4];
#pragma unroll
    for (int mt = 0; mt < 4; mt++)
        a_row[mt] = (uint32_t)(wm * 64 + mt * 16 + (jj & 1) * 8 + rr) * 128;
#pragma unroll
    for (int p = 0; p < 4; p++)
        b_row[p] = 16384u + (uint32_t)(wn * 64 + p * 16 + (jj & 1) * 8 + rr) * 128;
    const uint32_t colq = (uint32_t)(jj >> 1) * 16;

    for (int kt = 0; kt < nKt; kt++) {
        int stg = kt % 3;
        MBAR_WAIT(mb0 + stg * 8, (kt / 3) & 1);
        uint32_t stage = sb + stg * STG_BYT;

#pragma unroll
        for (int kc = 0; kc < 4; kc++) {
            uint32_t colb = (kc * 32 + colq) ^ xorv;
            uint32_t af[4][4];
#pragma unroll
            for (int mt = 0; mt < 4; mt++)
                ldmx4(af[mt][0], af[mt][1], af[mt][2], af[mt][3], stage + a_row[mt] + colb);
            uint32_t bf[8][2];
#pragma unroll
            for (int p = 0; p < 4; p++) {
                uint32_t r0, r1, r2, r3;
                ldmx4(r0, r1, r2, r3, stage + b_row[p] + colb);
                bf[2 * p][0] = r0; bf[2 * p + 1][0] = r1;
                bf[2 * p][1] = r2; bf[2 * p + 1][1] = r3;
            }
#pragma unroll
            for (int mt = 0; mt < 4; mt++)
#pragma unroll
                for (int nt = 0; nt < 8; nt++)
                    mma_f16(acc[mt][nt], af[mt], bf[nt]);
        }
        __syncthreads();
        if (tid == 0 && kt + 3 < nKt) {
            MBAR_EXPECT_TX(mb0 + stg * 8, STG_BYT);
            TMA_LOAD_3D(sb + stg * STG_BYT,         &tmA, (kt + 3) * 64, rowBase, 0,     mb0 + stg * 8);
            TMA_LOAD_3D(sb + stg * STG_BYT + 16384, &tmB, (kt + 3) * 64, colBase, layer, mb0 + stg * 8);
        }
    }

    // ---- epilogue ----
#pragma unroll
    for (int mt = 0; mt < 4; mt++) {
        int row0 = rowBase + wm * 64 + mt * 16 + qr;
#pragma unroll
        for (int nt = 0; nt < 8; nt++) {
            int col = colBase + wn * 64 + nt * 8 + qc * 2;
            float b0 = bias[col], b1 = bias[col + 1];
            float v0 = acc[mt][nt][0] + b0;
            float v1 = acc[mt][nt][1] + b1;
            float v2 = acc[mt][nt][2] + b0;
            float v3 = acc[mt][nt][3] + b1;
            if (act) { v0 = gelu_tanh(v0); v1 = gelu_tanh(v1); v2 = gelu_tanh(v2); v3 = gelu_tanh(v3); }
            if (Cf) {
                *(float2*)(Cf + (size_t)row0 * N + col)       = make_float2(v0, v1);
                *(float2*)(Cf + (size_t)(row0 + 8) * N + col) = make_float2(v2, v3);
            }
            if (Ch) {
                *(__half2*)(Ch + (size_t)row0 * N + col)       = __floats2half2_rn(v0, v1);
                *(__half2*)(Ch + (size_t)(row0 + 8) * N + col) = __floats2half2_rn(v2, v3);
            }
        }
    }
}

// ---------------- weight packing: transpose [K][N] f32 -> [N][K] half --------
__global__ void pack_weights_kernel(const float* __restrict__ Wq, const float* __restrict__ Wk,
                                    const float* __restrict__ Wv, const float* __restrict__ Wo,
                                    const float* __restrict__ W1, const float* __restrict__ W2) {
    __shared__ float t[32][33];
    int bid = blockIdx.x;
    int l = bid / 3072, tt = bid % 3072;
    const float* src; __half* dst; int Kd, Nd, tk, tn;
    if (tt < 768) {
        int which = tt / 256, r = tt % 256;
        src = (which == 0 ? Wq : which == 1 ? Wk : Wv) + (size_t)l * Dn * Dn;
        dst = g_WQKVh + (size_t)l * 1536 * Dn + (size_t)which * Dn * Dn;
        Kd = Dn; Nd = Dn; tk = r & 15; tn = r >> 4;
    } else if (tt < 1024) {
        int r = tt - 768;
        src = Wo + (size_t)l * Dn * Dn;
        dst = g_Woh + (size_t)l * Dn * Dn;
        Kd = Dn; Nd = Dn; tk = r & 15; tn = r >> 4;
    } else if (tt < 2048) {
        int r = tt - 1024;
        src = W1 + (size_t)l * Dn * FFNn;
        dst = g_W1h + (size_t)l * FFNn * Dn;
        Kd = Dn; Nd = FFNn; tk = r & 15; tn = r >> 4;
    } else {
        int r = tt - 2048;
        src = W2 + (size_t)l * FFNn * Dn;
        dst = g_W2h + (size_t)l * Dn * FFNn;
        Kd = FFNn; Nd = Dn; tk = r & 63; tn = r >> 6;
    }
    int k0 = tk * 32, n0 = tn * 32;
    int x = threadIdx.x, y = threadIdx.y;
#pragma unroll
    for (int i = 0; i < 32; i += 8)
        t[y + i][x] = src[(size_t)(k0 + y + i) * Nd + n0 + x];
    __syncthreads();
#pragma unroll
    for (int i = 0; i < 32; i += 8)
        dst[(size_t)(n0 + y + i) * Kd + k0 + x] = __float2half(t[x][y + i]);
}

__global__ void pack_bias_kernel(const float* __restrict__ bq, const float* __restrict__ bk,
                                 const float* __restrict__ bv) {
    int m = blockIdx.x * blockDim.x + threadIdx.x;
    if (m < Ln * Dn) {
        int l = m / Dn, c = m % Dn;
        g_bQKV[l * 1536 + c]        = bq[m];
        g_bQKV[l * 1536 + 512 + c]  = bk[m];
        g_bQKV[l * 1536 + 1024 + c] = bv[m];
    }
}

// ---------------- prep kernels ----------------------------------------------
__global__ void prep_x_kernel(const float* __restrict__ sup,
                              const float* __restrict__ cls) {
    int row = blockIdx.x;
    int s   = row & 7;
    int bq  = row >> 3;
    int b   = bq >> 5;
    int t   = threadIdx.x;
    float v = (s == 0) ? cls[t] : sup[(b * 7 + (s - 1)) * MDn + t];
    __half h = __float2half(v);
#pragma unroll
    for (int hh = 0; hh < 4; hh++) {
        g_X  [row * Dn + hh * MDn + t] = v;
        g_X16[row * Dn + hh * MDn + t] = h;
    }
}

__global__ void prep_t_kernel(const float* __restrict__ query_t,
                              const float* __restrict__ support_t) {
    int bq = blockIdx.x * blockDim.x + threadIdx.x;
    if (bq >= BQn) return;
    int b = bq >> 5, q = bq & 31;
    g_Tseq[bq * 8] = query_t[b * 32 + q];
#pragma unroll
    for (int f = 0; f < 7; f++)
        g_Tseq[bq * 8 + 1 + f] = support_t[b * 7 + f];
}

__global__ void prep_bias_kernel(const float* __restrict__ t_freq,
                                 const float* __restrict__ t_phase,
                                 const float* __restrict__ time_w) {
    int bq  = blockIdx.x;
    int tid = threadIdx.x;             // 64
    __shared__ float tw[Ln][TDn];
    __shared__ float fr[TDn], ph[TDn], ts[Sn];
    if (tid < TDn) { fr[tid] = t_freq[tid]; ph[tid] = t_phase[tid]; }
    if (tid < Sn)  ts[tid] = g_Tseq[bq * 8 + tid];
    for (int i = tid; i < Ln * TDn; i += 64) tw[i / TDn][i % TDn] = time_w[i];
    __syncthreads();
    int s = tid >> 3, t = tid & 7;
    float dt = ts[s] - ts[t];
    float acc[Ln];
#pragma unroll
    for (int l = 0; l < Ln; l++) acc[l] = 0.f;
    for (int td = 0; td < TDn; td++) {
        float c = cosf(dt * fr[td] + ph[td]);
#pragma unroll
        for (int l = 0; l < Ln; l++) acc[l] += c * tw[l][td];
    }
#pragma unroll
    for (int l = 0; l < Ln; l++)
        g_Bias[(l * BQn + bq) * 64 + tid] = acc[l];
}

// ---------------- fp32 SGEMM (small Wc projection only) ---------------------
__global__ __launch_bounds__(256, 2)
void sgemm_kernel(const float* __restrict__ A, const float* __restrict__ W,
                  const float* __restrict__ bias, float* __restrict__ C,
                  int M, int N, int K, int lda, int act) {
    __shared__ float As[8][128];
    __shared__ float Bs[8][128];
    const int tid = threadIdx.x;
    const int rowBase = blockIdx.y * 128;
    const int colBase = blockIdx.x * 128;
    const int ty = tid >> 4, tx = tid & 15;

    const int aRow = tid >> 1;
    const int aK   = (tid & 1) * 4;
    const int bRow = tid >> 5;
    const int bC4  = (tid & 31) * 4;
    const float* Ap = A + (rowBase + aRow) * lda + aK;
    const float* Wp = W + bRow * N + colBase + bC4;

    float acc[8][8];
#pragma unroll
    for (int i = 0; i < 8; i++)
#pragma unroll
        for (int j = 0; j < 8; j++) acc[i][j] = 0.f;

    for (int k0 = 0; k0 < K; k0 += 8) {
        float4 a = *(const float4*)(Ap + k0);
        As[aK + 0][aRow] = a.x;
        As[aK + 1][aRow] = a.y;
        As[aK + 2][aRow] = a.z;
        As[aK + 3][aRow] = a.w;
        *(float4*)&Bs[bRow][bC4] = *(const float4*)(Wp + (size_t)k0 * N);
        __syncthreads();
#pragma unroll
        for (int kk = 0; kk < 8; kk++) {
            float ra[8], rb[8];
#pragma unroll
            for (int i = 0; i < 8; i++) ra[i] = As[kk][ty * 8 + i];
#pragma unroll
            for (int j = 0; j < 4; j++) {
                rb[j]     = Bs[kk][tx * 4 + j];
                rb[j + 4] = Bs[kk][64 + tx * 4 + j];
            }
#pragma unroll
            for (int i = 0; i < 8; i++)
#pragma unroll
                for (int j = 0; j < 8; j++) acc[i][j] = fmaf(ra[i], rb[j], acc[i][j]);
        }
        __syncthreads();
    }
#pragma unroll
    for (int i = 0; i < 8; i++) {
        int row = rowBase + ty * 8 + i;
#pragma unroll
        for (int j = 0; j < 8; j++) {
            int col = colBase + ((j < 4) ? (tx * 4 + j) : (64 + tx * 4 + j - 4));
            float v = acc[i][j] + bias[col];
            if (act) {
                float x3 = v * v * v;
                v = 0.5f * v * (1.f + tanhf(0.7978845608028654f * (v + 0.044715f * x3)));
            }
            C[(size_t)row * N + col] = v;
        }
    }
}

// ---------------- attention on fused QKV buffer ------------------------------
__global__ void attn_kernel(const float* __restrict__ bias) {
    int j   = blockIdx.x;              // 0..BQ*H-1
    int tid = threadIdx.x;             // 128
    __shared__ float qs[8][128], ks[8][128], vs[8][128];
    __shared__ float sc[8][9];
    const float* base = g_QKV + (size_t)(j * 2) * 1536;   // raw reshape: j*1024 floats = 2 rows
#pragma unroll
    for (int s = 0; s < 8; s++) {
        int off = s * 128 + tid;
        int r = off >> 9, c = off & 511;
        const float* rp = base + (size_t)r * 1536 + c;
        qs[s][tid] = rp[0];
        ks[s][tid] = rp[512];
        vs[s][tid] = rp[1024];
    }
    __syncthreads();
    if (tid < 64) {
        int s = tid >> 3, t = tid & 7;
        float d = 0.f;
#pragma unroll
        for (int i = 0; i < 128; i++) d = fmaf(qs[s][i], ks[t][i], d);
        sc[s][t] = d * SCALE + bias[(j & (BQn - 1)) * 64 + tid];
    }
    __syncthreads();
    if (tid < 8) {
        int s = tid;
        float m = sc[s][0];
#pragma unroll
        for (int t = 1; t < 8; t++) m = fmaxf(m, sc[s][t]);
        float sum = 0.f;
#pragma unroll
        for (int t = 0; t < 8; t++) { float e = expf(sc[s][t] - m); sc[s][t] = e; sum += e; }
        float inv = 1.f / sum;
#pragma unroll
        for (int t = 0; t < 8; t++) sc[s][t] *= inv;
    }
    __syncthreads();
    __half* cp = g_Ctx16 + (size_t)j * 1024;
#pragma unroll
    for (int s = 0; s < 8; s++) {
        float a = 0.f;
#pragma unroll
        for (int t = 0; t < 8; t++) a = fmaf(sc[s][t], vs[t][tid], a);
        cp[s * 128 + tid] = __float2half(a);
    }
}

// ---------------- residual add + LayerNorm (fp32 + half outputs) ------------
__global__ void add_ln_kernel(const float* __restrict__ res, const float* __restrict__ add,
                              const float* __restrict__ g, const float* __restrict__ b,
                              float* __restrict__ out, __half* __restrict__ out16) {
    int row = blockIdx.x;
    int tid = threadIdx.x;             // 256
    float v0 = res[(size_t)row * Dn + tid]       + add[(size_t)row * Dn + tid];
    float v1 = res[(size_t)row * Dn + tid + 256] + add[(size_t)row * Dn + tid + 256];
    float s  = v0 + v1;
    float sq = v0 * v0 + v1 * v1;
#pragma unroll
    for (int o = 16; o > 0; o >>= 1) {
        s  += __shfl_xor_sync(0xffffffffu, s,  o);
        sq += __shfl_xor_sync(0xffffffffu, sq, o);
    }
    __shared__ float rs[8], rq[8];
    __shared__ float s_mean, s_inv;
    int w = tid >> 5;
    if ((tid & 31) == 0) { rs[w] = s; rq[w] = sq; }
    __syncthreads();
    if (tid == 0) {
        float ts = 0.f, tq = 0.f;
#pragma unroll
        for (int i = 0; i < 8; i++) { ts += rs[i]; tq += rq[i]; }
        float mean = ts * (1.f / Dn);
        float var  = tq * (1.f / Dn) - mean * mean;
        s_mean = mean;
        s_inv  = rsqrtf(var + 1e-5f);
    }
    __syncthreads();
    float mean = s_mean, inv = s_inv;
    float o0 = g[tid]       * (v0 - mean) * inv + b[tid];
    float o1 = g[tid + 256] * (v1 - mean) * inv + b[tid + 256];
    out[(size_t)row * Dn + tid]         = o0;
    out[(size_t)row * Dn + tid + 256]   = o1;
    out16[(size_t)row * Dn + tid]       = __float2half(o0);
    out16[(size_t)row * Dn + tid + 256] = __float2half(o1);
}

// ---------------- final BatchNorm (only s=0 channel needed) -----------------
__global__ void bn_zero_kernel() { g_Stats[0] = 0.f; g_Stats[1] = 0.f; }

__global__ void bn_reduce_kernel() {
    float s = 0.f, q = 0.f;
    for (int i = blockIdx.x * blockDim.x + threadIdx.x; i < BQn * MDn;
         i += gridDim.x * blockDim.x) {
        float v = g_Hc[i]; s += v; q += v * v;
    }
#pragma unroll
    for (int o = 16; o > 0; o >>= 1) {
        s += __shfl_xor_sync(0xffffffffu, s, o);
        q += __shfl_xor_sync(0xffffffffu, q, o);
    }
    __shared__ float rs[8], rq[8];
    int w = threadIdx.x >> 5;
    if ((threadIdx.x & 31) == 0) { rs[w] = s; rq[w] = q; }
    __syncthreads();
    if (threadIdx.x == 0) {
        float ts = 0.f, tq = 0.f;
#pragma unroll
        for (int i = 0; i < 8; i++) { ts += rs[i]; tq += rq[i]; }
        atomicAdd(&g_Stats[0], ts);
        atomicAdd(&g_Stats[1], tq);
    }
}

__global__ void bn_final_kernel(const float* __restrict__ bn_g,
                                const float* __restrict__ bn_b,
                                float* __restrict__ out) {
    const float invN = 1.f / (float)(BQn * MDn);
    float mu  = g_Stats[0] * invN;
    float var = g_Stats[1] * invN - mu * mu;
    float inv = rsqrtf(var + 1e-5f);
    float gg = bn_g[0], bb = bn_b[0];
    for (int i = blockIdx.x * blockDim.x + threadIdx.x; i < BQn * MDn;
         i += gridDim.x * blockDim.x) {
        float h = gg * (g_Hc[i] - mu) * inv + bb;
        out[i] = (h >= 0.f) ? h : 0.01f * h;
    }
}

// ---------------- host orchestration ----------------------------------------
typedef CUresult (*PFN_tmencode)(
    CUtensorMap*, CUtensorMapDataType, cuuint32_t, void*,
    const cuuint64_t*, const cuuint64_t*, const cuuint32_t*, const cuuint32_t*,
    CUtensorMapInterleave, CUtensorMapSwizzle, CUtensorMapL2promotion,
    CUtensorMapFloatOOBfill);

static void make_map_h16(PFN_tmencode enc, CUtensorMap* m, void* ptr,
                         unsigned long long K, unsigned long long rows,
                         unsigned long long L, unsigned boxRows) {
    cuuint64_t dims[3]    = {K, rows, L};
    cuuint64_t strides[2] = {K * 2ull, rows * K * 2ull};
    cuuint32_t box[3]     = {64u, boxRows, 1u};
    cuuint32_t es[3]      = {1u, 1u, 1u};
    enc(m, CU_TENSOR_MAP_DATA_TYPE_UINT16, 3, ptr, dims, strides, box, es,
        CU_TENSOR_MAP_INTERLEAVE_NONE, CU_TENSOR_MAP_SWIZZLE_128B,
        CU_TENSOR_MAP_L2_PROMOTION_L2_128B, CU_TENSOR_MAP_FLOAT_OOB_FILL_NONE);
}

extern "C" void kernel_launch(void* const* d_in, const int* in_sizes, int n_in,
                              void* d_out, int out_size) {
    const float* sup    = (const float*)d_in[0];
    const float* qt     = (const float*)d_in[1];
    const float* st     = (const float*)d_in[2];
    const float* cls    = (const float*)d_in[3];
    const float* tfreq  = (const float*)d_in[4];
    const float* tphase = (const float*)d_in[5];
    const float* Wq = (const float*)d_in[6];
    const float* bq = (const float*)d_in[7];
    const float* Wk = (const float*)d_in[8];
    const float* bk = (const float*)d_in[9];
    const float* Wv = (const float*)d_in[10];
    const float* bv = (const float*)d_in[11];
    const float* Wo = (const float*)d_in[12];
    const float* bo = (const float*)d_in[13];
    const float* ln1g = (const float*)d_in[14];
    const float* ln1b = (const float*)d_in[15];
    const float* tw   = (const float*)d_in[16];
    const float* W1 = (const float*)d_in[17];
    const float* b1 = (const float*)d_in[18];
    const float* W2 = (const float*)d_in[19];
    const float* b2 = (const float*)d_in[20];
    const float* ln2g = (const float*)d_in[21];
    const float* ln2b = (const float*)d_in[22];
    const float* Wc = (const float*)d_in[23];
    const float* bc = (const float*)d_in[24];
    const float* bng = (const float*)d_in[25];
    const float* bnb = (const float*)d_in[26];
    float* out = (float*)d_out;

    float *X, *QKV, *Tmp, *Out1, *Hc, *Bias, *bQKVp;
    __half *X16, *Ctx16, *O116, *Ffn16, *WQKVh, *Woh, *W1h, *W2h;
    cudaGetSymbolAddress((void**)&X,     g_X);
    cudaGetSymbolAddress((void**)&X16,   g_X16);
    cudaGetSymbolAddress((void**)&QKV,   g_QKV);
    cudaGetSymbolAddress((void**)&Ctx16, g_Ctx16);
    cudaGetSymbolAddress((void**)&Tmp,   g_Tmp);
    cudaGetSymbolAddress((void**)&Out1,  g_Out1);
    cudaGetSymbolAddress((void**)&O116,  g_O116);
    cudaGetSymbolAddress((void**)&Ffn16, g_Ffn16);
    cudaGetSymbolAddress((void**)&Hc,    g_Hc);
    cudaGetSymbolAddress((void**)&Bias,  g_Bias);
    cudaGetSymbolAddress((void**)&bQKVp, g_bQKV);
    cudaGetSymbolAddress((void**)&WQKVh, g_WQKVh);
    cudaGetSymbolAddress((void**)&Woh,   g_Woh);
    cudaGetSymbolAddress((void**)&W1h,   g_W1h);
    cudaGetSymbolAddress((void**)&W2h,   g_W2h);

    // driver entry point for tensormap encode (no -lcuda at link time)
    PFN_tmencode enc = nullptr;
    {
        void* p = nullptr;
        cudaDriverEntryPointQueryResult qr;
        cudaGetDriverEntryPointByVersion("cuTensorMapEncodeTiled", &p, 12000,
                                         cudaEnableDefault, &qr);
        if (!p)
            cudaGetDriverEntryPoint("cuTensorMapEncodeTiled", &p, cudaEnableDefault, &qr);
        enc = (PFN_tmencode)p;
    }

    cudaFuncSetAttribute(hgemm_kernel,
                         cudaFuncAttributeMaxDynamicSharedMemorySize, HG_SMEM);

    CUtensorMap mX, mCtx, mO1, mFfn, mWqkv, mWo, mW1, mW2;
    make_map_h16(enc, &mX,   X16,   Dn,   ROWSn, 1,  128);
    make_map_h16(enc, &mCtx, Ctx16, Dn,   ROWSn, 1,  128);
    make_map_h16(enc, &mO1,  O116,  Dn,   ROWSn, 1,  128);
    make_map_h16(enc, &mFfn, Ffn16, FFNn, ROWSn, 1,  128);
    make_map_h16(enc, &mWqkv, WQKVh, Dn,   1536, Ln, 256);
    make_map_h16(enc, &mWo,   Woh,   Dn,   Dn,   Ln, 256);
    make_map_h16(enc, &mW1,   W1h,   Dn,   FFNn, Ln, 256);
    make_map_h16(enc, &mW2,   W2h,   FFNn, Dn,   Ln, 256);

    pack_weights_kernel<<<Ln * 3072, dim3(32, 8)>>>(Wq, Wk, Wv, Wo, W1, W2);
    pack_bias_kernel<<<12, 256>>>(bq, bk, bv);
    prep_x_kernel<<<ROWSn, 128>>>(sup, cls);
    prep_t_kernel<<<16, 256>>>(qt, st);
    prep_bias_kernel<<<BQn, 64>>>(tfreq, tphase, tw);

    const dim3 gQKV(1536 / 256, ROWSn / 128);   // 6 x 256
    const dim3 gD(Dn / 256, ROWSn / 128);       // 2 x 256
    const dim3 gF(FFNn / 256, ROWSn / 128);     // 8 x 256

    for (int l = 0; l < Ln; l++) {
        const float* bqkv = bQKVp + (size_t)l * 1536;

        hgemm_kernel<<<gQKV, 256, HG_SMEM>>>(mX, mWqkv, bqkv, QKV, nullptr, 1536, Dn / 64, l, 0);

        attn_kernel<<<BQn * 4, 128>>>(Bias + (size_t)l * BQn * 64);

        hgemm_kernel<<<gD, 256, HG_SMEM>>>(mCtx, mWo, bo + l * Dn, Tmp, nullptr, Dn, Dn / 64, l, 0);
        add_ln_kernel<<<ROWSn, 256>>>(X, Tmp, ln1g + l * Dn, ln1b + l * Dn, Out1, O116);

        hgemm_kernel<<<gF, 256, HG_SMEM>>>(mO1, mW1, b1 + l * FFNn, nullptr, Ffn16, FFNn, Dn / 64, l, 1);
        hgemm_kernel<<<gD, 256, HG_SMEM>>>(mFfn, mW2, b2 + l * Dn, Tmp, nullptr, Dn, FFNn / 64, l, 0);
        add_ln_kernel<<<ROWSn, 256>>>(Out1, Tmp, ln2g + l * Dn, ln2b + l * Dn, X, X16);
    }

    // compress: only s=0 rows feed the output (exact fp32 path)
    sgemm_kernel<<<dim3(1, 32), 256>>>(X, Wc, bc, Hc, BQn, MDn, Dn, Sn * Dn, 0);
    bn_zero_kernel<<<1, 1>>>();
    bn_reduce_kernel<<<256, 256>>>();
    bn_final_kernel<<<2048, 256>>>(bng, bnb, out);

    (void)in_sizes; (void)n_in; (void)out_size;
}

// round 8
// speedup vs baseline: 5.0352x; 1.0422x over previous
#include <cuda_runtime.h>
#include <cuda.h>
#include <cuda_fp16.h>
#include <math.h>
#include <stdint.h>

#define BQn   4096
#define Sn    8
#define Dn    512
#define MDn   128
#define Ln    6
#define FFNn  2048
#define TDn   32
#define ROWSn (BQn * Sn)          /* 32768 */
#define SCALE 0.17677669529663687f /* 32^-0.5 */

// ---------------- scratch (device globals; no allocation allowed) -----------
__device__ float  g_X    [ROWSn * Dn];
__device__ __align__(1024) __half g_X16  [ROWSn * Dn];
__device__ __align__(1024) __half g_QKV16[ROWSn * 3 * Dn];
__device__ __align__(1024) __half g_Ctx16[ROWSn * Dn];
__device__ float  g_Tmp  [ROWSn * Dn];
__device__ float  g_Out1 [ROWSn * Dn];
__device__ __align__(1024) __half g_O116 [ROWSn * Dn];
__device__ __align__(1024) __half g_Ffn16[ROWSn * FFNn];
__device__ float  g_Bias [Ln * BQn * 64];
__device__ float  g_Tseq [BQn * Sn];
__device__ float  g_Hc   [BQn * MDn];
__device__ float  g_Stats[2];
__device__ __align__(1024) __half g_WQKVh[Ln * 1536 * Dn];   /* [l][n(q|k|v)][k] */
__device__ float  g_bQKV [Ln * 1536];
__device__ __align__(1024) __half g_Woh  [Ln * Dn * Dn];     /* [l][n][k] */
__device__ __align__(1024) __half g_W1h  [Ln * FFNn * Dn];   /* [l][n][k] */
__device__ __align__(1024) __half g_W2h  [Ln * Dn * FFNn];   /* [l][n][k] */

// ---------------- helpers ----------------------------------------------------
__device__ __forceinline__ float gelu_tanh(float v) {
    return 0.5f * v * (1.f + tanhf(0.7978845608028654f * (v + 0.044715f * v * v * v)));
}
__device__ __forceinline__ uint32_t smem_u32(const void* p) {
    uint32_t a;
    asm("{ .reg .u64 t; cvta.to.shared.u64 t, %1; cvt.u32.u64 %0, t; }" : "=r"(a) : "l"(p));
    return a;
}

#define MBAR_INIT(addr, cnt) \
    asm volatile("mbarrier.init.shared.b64 [%0], %1;" :: "r"(addr), "r"((uint32_t)(cnt)) : "memory")
#define MBAR_EXPECT_TX(addr, bytes) \
    asm volatile("mbarrier.arrive.expect_tx.shared.b64 _, [%0], %1;" :: "r"(addr), "r"((uint32_t)(bytes)) : "memory")
#define MBAR_ARRIVE(addr) \
    asm volatile("mbarrier.arrive.shared.b64 _, [%0];" :: "r"(addr) : "memory")
#define MBAR_WAIT(addr, parity) do {                                                   \
    uint32_t _m = (addr); uint32_t _p = (parity); uint32_t _d;                         \
    asm volatile("{\n\t.reg .pred p;\n\t"                                              \
        "mbarrier.try_wait.parity.acquire.cta.shared::cta.b64 p, [%1], %2;\n\t"        \
        "selp.b32 %0, 1, 0, p;\n\t}" : "=r"(_d) : "r"(_m), "r"(_p) : "memory");        \
    if (!_d) {                                                                         \
        asm volatile("{\n\t.reg .pred P1;\n\t"                                         \
            "W_%=:\n\t"                                                                \
            "mbarrier.try_wait.parity.acquire.cta.shared::cta.b64 P1, [%0], %1, 0x989680;\n\t" \
            "@P1 bra.uni D_%=;\n\t"                                                    \
            "bra.uni W_%=;\n\t"                                                        \
            "D_%=:\n\t}" :: "r"(_m), "r"(_p) : "memory");                              \
    }                                                                                  \
} while (0)

#define TMA_LOAD_3D(smem, map, x, y, z, mbar)                                             \
    asm volatile("cp.async.bulk.tensor.3d.shared::cta.global.tile.mbarrier::complete_tx::bytes " \
                 "[%0], [%1, {%2, %3, %4}], [%5];"                                        \
                 :: "r"((uint32_t)(smem)), "l"(map), "r"((int)(x)), "r"((int)(y)),        \
                    "r"((int)(z)), "r"((uint32_t)(mbar)) : "memory")

__device__ __forceinline__ void ldmx4(uint32_t& r0, uint32_t& r1, uint32_t& r2, uint32_t& r3,
                                      uint32_t addr) {
    asm volatile("ldmatrix.sync.aligned.m8n8.x4.shared.b16 {%0,%1,%2,%3}, [%4];"
                 : "=r"(r0), "=r"(r1), "=r"(r2), "=r"(r3) : "r"(addr));
}
__device__ __forceinline__ void mma_f16(float* c, const uint32_t* a, const uint32_t* b) {
    asm volatile(
        "mma.sync.aligned.m16n8k16.row.col.f32.f16.f16.f32 "
        "{%0,%1,%2,%3}, {%4,%5,%6,%7}, {%8,%9}, {%0,%1,%2,%3};"
        : "+f"(c[0]), "+f"(c[1]), "+f"(c[2]), "+f"(c[3])
        : "r"(a[0]), "r"(a[1]), "r"(a[2]), "r"(a[3]), "r"(b[0]), "r"(b[1]));
}

// ---------------- fp16 TMA + mma.sync GEMM -----------------------------------
// C[M,N] = A[M,K] @ Bt[N,K]^T + bias.  CTA 128x256, 8 warps (2x4),
// warp tile 64x64.  K chunks of 64 halves (128B rows, SW128), 4-stage TMA.
// Per-stage full (tx) + empty (256-arrive) mbarriers; no CTA-wide syncthreads
// in the mainloop.
#define NSTG     4
#define STG_BYT  49152
#define HG_SMEM  (NSTG * STG_BYT + 1024)

__global__ __launch_bounds__(256, 1)
void hgemm_kernel(const __grid_constant__ CUtensorMap tmA,
                  const __grid_constant__ CUtensorMap tmB,
                  const float* __restrict__ bias, float* __restrict__ Cf,
                  __half* __restrict__ Ch,
                  int N, int nKt, int layer, int act) {
    extern __shared__ char smraw[];
    __shared__ __align__(8) uint64_t mbar[2 * NSTG];   // [0..3] full, [4..7] empty
    uint32_t sb = (smem_u32(smraw) + 1023u) & ~1023u;
    uint32_t mbF = smem_u32(&mbar[0]);
    uint32_t mbE = smem_u32(&mbar[NSTG]);

    const int tid  = threadIdx.x;
    const int lane = tid & 31, warp = tid >> 5;
    const int wm = warp & 1, wn = warp >> 1;
    const int qr = lane >> 2, qc = lane & 3;
    const int jj = lane >> 3, rr = lane & 7;
    const int rowBase = blockIdx.y * 128;
    const int colBase = blockIdx.x * 256;

    if (tid == 0) {
#pragma unroll
        for (int s = 0; s < NSTG; s++) {
            MBAR_INIT(mbF + s * 8, 1);
            MBAR_INIT(mbE + s * 8, 256);
        }
    }
    __syncthreads();

    if (tid == 0) {
        int pre = nKt < NSTG ? nKt : NSTG;
        for (int s = 0; s < pre; s++) {
            MBAR_EXPECT_TX(mbF + s * 8, STG_BYT);
            TMA_LOAD_3D(sb + s * STG_BYT,         &tmA, s * 64, rowBase, 0,     mbF + s * 8);
            TMA_LOAD_3D(sb + s * STG_BYT + 16384, &tmB, s * 64, colBase, layer, mbF + s * 8);
        }
    }

    float acc[4][8][4];
#pragma unroll
    for (int i = 0; i < 4; i++)
#pragma unroll
        for (int j = 0; j < 8; j++)
#pragma unroll
            for (int k = 0; k < 4; k++) acc[i][j][k] = 0.f;

    // ldmatrix swizzled addressing: addr = base + row*128 + (colb ^ (rr<<4))
    const uint32_t xorv = (uint32_t)rr << 4;
    uint32_t a_row[4], b_row[4];
#pragma unroll
    for (int mt = 0; mt < 4; mt++)
        a_row[mt] = (uint32_t)(wm * 64 + mt * 16 + (jj & 1) * 8 + rr) * 128;
#pragma unroll
    for (int p = 0; p < 4; p++)
        b_row[p] = 16384u + (uint32_t)(wn * 64 + p * 16 + (jj & 1) * 8 + rr) * 128;
    const uint32_t colq = (uint32_t)(jj >> 1) * 16;

    for (int kt = 0; kt < nKt; kt++) {
        int stg = kt & (NSTG - 1);
        int ph  = (kt / NSTG) & 1;
        MBAR_WAIT(mbF + stg * 8, ph);
        uint32_t stage = sb + stg * STG_BYT;

#pragma unroll
        for (int kc = 0; kc < 4; kc++) {
            uint32_t colb = (kc * 32 + colq) ^ xorv;
            uint32_t af[4][4];
#pragma unroll
            for (int mt = 0; mt < 4; mt++)
                ldmx4(af[mt][0], af[mt][1], af[mt][2], af[mt][3], stage + a_row[mt] + colb);
            uint32_t bf[8][2];
#pragma unroll
            for (int p = 0; p < 4; p++) {
                uint32_t r0, r1, r2, r3;
                ldmx4(r0, r1, r2, r3, stage + b_row[p] + colb);
                bf[2 * p][0] = r0; bf[2 * p + 1][0] = r1;
                bf[2 * p][1] = r2; bf[2 * p + 1][1] = r3;
            }
#pragma unroll
            for (int mt = 0; mt < 4; mt++)
#pragma unroll
                for (int nt = 0; nt < 8; nt++)
                    mma_f16(acc[mt][nt], af[mt], bf[nt]);
        }
        // signal this stage consumed (registers hold all fragments now)
        MBAR_ARRIVE(mbE + stg * 8);
        if (tid == 0 && kt + NSTG < nKt) {
            MBAR_WAIT(mbE + stg * 8, ph);       // all 256 consumed it
            MBAR_EXPECT_TX(mbF + stg * 8, STG_BYT);
            TMA_LOAD_3D(sb + stg * STG_BYT,         &tmA, (kt + NSTG) * 64, rowBase, 0,     mbF + stg * 8);
            TMA_LOAD_3D(sb + stg * STG_BYT + 16384, &tmB, (kt + NSTG) * 64, colBase, layer, mbF + stg * 8);
        }
    }

    // ---- epilogue ----
#pragma unroll
    for (int mt = 0; mt < 4; mt++) {
        int row0 = rowBase + wm * 64 + mt * 16 + qr;
#pragma unroll
        for (int nt = 0; nt < 8; nt++) {
            int col = colBase + wn * 64 + nt * 8 + qc * 2;
            float b0 = bias[col], b1 = bias[col + 1];
            float v0 = acc[mt][nt][0] + b0;
            float v1 = acc[mt][nt][1] + b1;
            float v2 = acc[mt][nt][2] + b0;
            float v3 = acc[mt][nt][3] + b1;
            if (act) { v0 = gelu_tanh(v0); v1 = gelu_tanh(v1); v2 = gelu_tanh(v2); v3 = gelu_tanh(v3); }
            if (Cf) {
                *(float2*)(Cf + (size_t)row0 * N + col)       = make_float2(v0, v1);
                *(float2*)(Cf + (size_t)(row0 + 8) * N + col) = make_float2(v2, v3);
            }
            if (Ch) {
                *(__half2*)(Ch + (size_t)row0 * N + col)       = __floats2half2_rn(v0, v1);
                *(__half2*)(Ch + (size_t)(row0 + 8) * N + col) = __floats2half2_rn(v2, v3);
            }
        }
    }
}

// ---------------- weight packing: transpose [K][N] f32 -> [N][K] half --------
__global__ void pack_weights_kernel(const float* __restrict__ Wq, const float* __restrict__ Wk,
                                    const float* __restrict__ Wv, const float* __restrict__ Wo,
                                    const float* __restrict__ W1, const float* __restrict__ W2) {
    __shared__ float t[32][33];
    int bid = blockIdx.x;
    int l = bid / 3072, tt = bid % 3072;
    const float* src; __half* dst; int Kd, Nd, tk, tn;
    if (tt < 768) {
        int which = tt / 256, r = tt % 256;
        src = (which == 0 ? Wq : which == 1 ? Wk : Wv) + (size_t)l * Dn * Dn;
        dst = g_WQKVh + (size_t)l * 1536 * Dn + (size_t)which * Dn * Dn;
        Kd = Dn; Nd = Dn; tk = r & 15; tn = r >> 4;
    } else if (tt < 1024) {
        int r = tt - 768;
        src = Wo + (size_t)l * Dn * Dn;
        dst = g_Woh + (size_t)l * Dn * Dn;
        Kd = Dn; Nd = Dn; tk = r & 15; tn = r >> 4;
    } else if (tt < 2048) {
        int r = tt - 1024;
        src = W1 + (size_t)l * Dn * FFNn;
        dst = g_W1h + (size_t)l * FFNn * Dn;
        Kd = Dn; Nd = FFNn; tk = r & 15; tn = r >> 4;
    } else {
        int r = tt - 2048;
        src = W2 + (size_t)l * FFNn * Dn;
        dst = g_W2h + (size_t)l * Dn * FFNn;
        Kd = FFNn; Nd = Dn; tk = r & 63; tn = r >> 6;
    }
    int k0 = tk * 32, n0 = tn * 32;
    int x = threadIdx.x, y = threadIdx.y;
#pragma unroll
    for (int i = 0; i < 32; i += 8)
        t[y + i][x] = src[(size_t)(k0 + y + i) * Nd + n0 + x];
    __syncthreads();
#pragma unroll
    for (int i = 0; i < 32; i += 8)
        dst[(size_t)(n0 + y + i) * Kd + k0 + x] = __float2half(t[x][y + i]);
}

__global__ void pack_bias_kernel(const float* __restrict__ bq, const float* __restrict__ bk,
                                 const float* __restrict__ bv) {
    int m = blockIdx.x * blockDim.x + threadIdx.x;
    if (m < Ln * Dn) {
        int l = m / Dn, c = m % Dn;
        g_bQKV[l * 1536 + c]        = bq[m];
        g_bQKV[l * 1536 + 512 + c]  = bk[m];
        g_bQKV[l * 1536 + 1024 + c] = bv[m];
    }
}

// ---------------- prep kernels ----------------------------------------------
__global__ void prep_x_kernel(const float* __restrict__ sup,
                              const float* __restrict__ cls) {
    int row = blockIdx.x;
    int s   = row & 7;
    int bq  = row >> 3;
    int b   = bq >> 5;
    int t   = threadIdx.x;
    float v = (s == 0) ? cls[t] : sup[(b * 7 + (s - 1)) * MDn + t];
    __half h = __float2half(v);
#pragma unroll
    for (int hh = 0; hh < 4; hh++) {
        g_X  [row * Dn + hh * MDn + t] = v;
        g_X16[row * Dn + hh * MDn + t] = h;
    }
}

__global__ void prep_t_kernel(const float* __restrict__ query_t,
                              const float* __restrict__ support_t) {
    int bq = blockIdx.x * blockDim.x + threadIdx.x;
    if (bq >= BQn) return;
    int b = bq >> 5, q = bq & 31;
    g_Tseq[bq * 8] = query_t[b * 32 + q];
#pragma unroll
    for (int f = 0; f < 7; f++)
        g_Tseq[bq * 8 + 1 + f] = support_t[b * 7 + f];
}

__global__ void prep_bias_kernel(const float* __restrict__ t_freq,
                                 const float* __restrict__ t_phase,
                                 const float* __restrict__ time_w) {
    int bq  = blockIdx.x;
    int tid = threadIdx.x;             // 64
    __shared__ float tw[Ln][TDn];
    __shared__ float fr[TDn], ph[TDn], ts[Sn];
    if (tid < TDn) { fr[tid] = t_freq[tid]; ph[tid] = t_phase[tid]; }
    if (tid < Sn)  ts[tid] = g_Tseq[bq * 8 + tid];
    for (int i = tid; i < Ln * TDn; i += 64) tw[i / TDn][i % TDn] = time_w[i];
    __syncthreads();
    int s = tid >> 3, t = tid & 7;
    float dt = ts[s] - ts[t];
    float acc[Ln];
#pragma unroll
    for (int l = 0; l < Ln; l++) acc[l] = 0.f;
    for (int td = 0; td < TDn; td++) {
        float c = cosf(dt * fr[td] + ph[td]);
#pragma unroll
        for (int l = 0; l < Ln; l++) acc[l] += c * tw[l][td];
    }
#pragma unroll
    for (int l = 0; l < Ln; l++)
        g_Bias[(l * BQn + bq) * 64 + tid] = acc[l];
}

// ---------------- fp32 SGEMM (small Wc projection only) ---------------------
__global__ __launch_bounds__(256, 2)
void sgemm_kernel(const float* __restrict__ A, const float* __restrict__ W,
                  const float* __restrict__ bias, float* __restrict__ C,
                  int M, int N, int K, int lda, int act) {
    __shared__ float As[8][128];
    __shared__ float Bs[8][128];
    const int tid = threadIdx.x;
    const int rowBase = blockIdx.y * 128;
    const int colBase = blockIdx.x * 128;
    const int ty = tid >> 4, tx = tid & 15;

    const int aRow = tid >> 1;
    const int aK   = (tid & 1) * 4;
    const int bRow = tid >> 5;
    const int bC4  = (tid & 31) * 4;
    const float* Ap = A + (rowBase + aRow) * lda + aK;
    const float* Wp = W + bRow * N + colBase + bC4;

    float acc[8][8];
#pragma unroll
    for (int i = 0; i < 8; i++)
#pragma unroll
        for (int j = 0; j < 8; j++) acc[i][j] = 0.f;

    for (int k0 = 0; k0 < K; k0 += 8) {
        float4 a = *(const float4*)(Ap + k0);
        As[aK + 0][aRow] = a.x;
        As[aK + 1][aRow] = a.y;
        As[aK + 2][aRow] = a.z;
        As[aK + 3][aRow] = a.w;
        *(float4*)&Bs[bRow][bC4] = *(const float4*)(Wp + (size_t)k0 * N);
        __syncthreads();
#pragma unroll
        for (int kk = 0; kk < 8; kk++) {
            float ra[8], rb[8];
#pragma unroll
            for (int i = 0; i < 8; i++) ra[i] = As[kk][ty * 8 + i];
#pragma unroll
            for (int j = 0; j < 4; j++) {
                rb[j]     = Bs[kk][tx * 4 + j];
                rb[j + 4] = Bs[kk][64 + tx * 4 + j];
            }
#pragma unroll
            for (int i = 0; i < 8; i++)
#pragma unroll
                for (int j = 0; j < 8; j++) acc[i][j] = fmaf(ra[i], rb[j], acc[i][j]);
        }
        __syncthreads();
    }
#pragma unroll
    for (int i = 0; i < 8; i++) {
        int row = rowBase + ty * 8 + i;
#pragma unroll
        for (int j = 0; j < 8; j++) {
            int col = colBase + ((j < 4) ? (tx * 4 + j) : (64 + tx * 4 + j - 4));
            float v = acc[i][j] + bias[col];
            if (act) {
                float x3 = v * v * v;
                v = 0.5f * v * (1.f + tanhf(0.7978845608028654f * (v + 0.044715f * x3)));
            }
            C[(size_t)row * N + col] = v;
        }
    }
}

// ---------------- attention on fused fp16 QKV buffer -------------------------
__global__ void attn_kernel(const float* __restrict__ bias) {
    int j   = blockIdx.x;              // 0..BQ*H-1
    int tid = threadIdx.x;             // 128
    __shared__ float qs[8][128], ks[8][128], vs[8][128];
    __shared__ float sc[8][9];
    const __half* base = g_QKV16 + (size_t)(j * 2) * 1536;  // raw reshape: j*1024 elems = 2 rows
#pragma unroll
    for (int s = 0; s < 8; s++) {
        int off = s * 128 + tid;
        int r = off >> 9, c = off & 511;
        const __half* rp = base + (size_t)r * 1536 + c;
        qs[s][tid] = __half2float(rp[0]);
        ks[s][tid] = __half2float(rp[512]);
        vs[s][tid] = __half2float(rp[1024]);
    }
    __syncthreads();
    if (tid < 64) {
        int s = tid >> 3, t = tid & 7;
        float d = 0.f;
#pragma unroll
        for (int i = 0; i < 128; i++) d = fmaf(qs[s][i], ks[t][i], d);
        sc[s][t] = d * SCALE + bias[(j & (BQn - 1)) * 64 + tid];
    }
    __syncthreads();
    if (tid < 8) {
        int s = tid;
        float m = sc[s][0];
#pragma unroll
        for (int t = 1; t < 8; t++) m = fmaxf(m, sc[s][t]);
        float sum = 0.f;
#pragma unroll
        for (int t = 0; t < 8; t++) { float e = expf(sc[s][t] - m); sc[s][t] = e; sum += e; }
        float inv = 1.f / sum;
#pragma unroll
        for (int t = 0; t < 8; t++) sc[s][t] *= inv;
    }
    __syncthreads();
    __half* cp = g_Ctx16 + (size_t)j * 1024;
#pragma unroll
    for (int s = 0; s < 8; s++) {
        float a = 0.f;
#pragma unroll
        for (int t = 0; t < 8; t++) a = fmaf(sc[s][t], vs[t][tid], a);
        cp[s * 128 + tid] = __float2half(a);
    }
}

// ---------------- residual add + LayerNorm (fp32 + half outputs) ------------
__global__ void add_ln_kernel(const float* __restrict__ res, const float* __restrict__ add,
                              const float* __restrict__ g, const float* __restrict__ b,
                              float* __restrict__ out, __half* __restrict__ out16) {
    int row = blockIdx.x;
    int tid = threadIdx.x;             // 256
    float v0 = res[(size_t)row * Dn + tid]       + add[(size_t)row * Dn + tid];
    float v1 = res[(size_t)row * Dn + tid + 256] + add[(size_t)row * Dn + tid + 256];
    float s  = v0 + v1;
    float sq = v0 * v0 + v1 * v1;
#pragma unroll
    for (int o = 16; o > 0; o >>= 1) {
        s  += __shfl_xor_sync(0xffffffffu, s,  o);
        sq += __shfl_xor_sync(0xffffffffu, sq, o);
    }
    __shared__ float rs[8], rq[8];
    __shared__ float s_mean, s_inv;
    int w = tid >> 5;
    if ((tid & 31) == 0) { rs[w] = s; rq[w] = sq; }
    __syncthreads();
    if (tid == 0) {
        float ts = 0.f, tq = 0.f;
#pragma unroll
        for (int i = 0; i < 8; i++) { ts += rs[i]; tq += rq[i]; }
        float mean = ts * (1.f / Dn);
        float var  = tq * (1.f / Dn) - mean * mean;
        s_mean = mean;
        s_inv  = rsqrtf(var + 1e-5f);
    }
    __syncthreads();
    float mean = s_mean, inv = s_inv;
    float o0 = g[tid]       * (v0 - mean) * inv + b[tid];
    float o1 = g[tid + 256] * (v1 - mean) * inv + b[tid + 256];
    out[(size_t)row * Dn + tid]         = o0;
    out[(size_t)row * Dn + tid + 256]   = o1;
    out16[(size_t)row * Dn + tid]       = __float2half(o0);
    out16[(size_t)row * Dn + tid + 256] = __float2half(o1);
}

// ---------------- final BatchNorm (only s=0 channel needed) -----------------
__global__ void bn_zero_kernel() { g_Stats[0] = 0.f; g_Stats[1] = 0.f; }

__global__ void bn_reduce_kernel() {
    float s = 0.f, q = 0.f;
    for (int i = blockIdx.x * blockDim.x + threadIdx.x; i < BQn * MDn;
         i += gridDim.x * blockDim.x) {
        float v = g_Hc[i]; s += v; q += v * v;
    }
#pragma unroll
    for (int o = 16; o > 0; o >>= 1) {
        s += __shfl_xor_sync(0xffffffffu, s, o);
        q += __shfl_xor_sync(0xffffffffu, q, o);
    }
    __shared__ float rs[8], rq[8];
    int w = threadIdx.x >> 5;
    if ((threadIdx.x & 31) == 0) { rs[w] = s; rq[w] = q; }
    __syncthreads();
    if (threadIdx.x == 0) {
        float ts = 0.f, tq = 0.f;
#pragma unroll
        for (int i = 0; i < 8; i++) { ts += rs[i]; tq += rq[i]; }
        atomicAdd(&g_Stats[0], ts);
        atomicAdd(&g_Stats[1], tq);
    }
}

__global__ void bn_final_kernel(const float* __restrict__ bn_g,
                                const float* __restrict__ bn_b,
                                float* __restrict__ out) {
    const float invN = 1.f / (float)(BQn * MDn);
    float mu  = g_Stats[0] * invN;
    float var = g_Stats[1] * invN - mu * mu;
    float inv = rsqrtf(var + 1e-5f);
    float gg = bn_g[0], bb = bn_b[0];
    for (int i = blockIdx.x * blockDim.x + threadIdx.x; i < BQn * MDn;
         i += gridDim.x * blockDim.x) {
        float h = gg * (g_Hc[i] - mu) * inv + bb;
        out[i] = (h >= 0.f) ? h : 0.01f * h;
    }
}

// ---------------- host orchestration ----------------------------------------
typedef CUresult (*PFN_tmencode)(
    CUtensorMap*, CUtensorMapDataType, cuuint32_t, void*,
    const cuuint64_t*, const cuuint64_t*, const cuuint32_t*, const cuuint32_t*,
    CUtensorMapInterleave, CUtensorMapSwizzle, CUtensorMapL2promotion,
    CUtensorMapFloatOOBfill);

static void make_map_h16(PFN_tmencode enc, CUtensorMap* m, void* ptr,
                         unsigned long long K, unsigned long long rows,
                         unsigned long long L, unsigned boxRows) {
    cuuint64_t dims[3]    = {K, rows, L};
    cuuint64_t strides[2] = {K * 2ull, rows * K * 2ull};
    cuuint32_t box[3]     = {64u, boxRows, 1u};
    cuuint32_t es[3]      = {1u, 1u, 1u};
    enc(m, CU_TENSOR_MAP_DATA_TYPE_UINT16, 3, ptr, dims, strides, box, es,
        CU_TENSOR_MAP_INTERLEAVE_NONE, CU_TENSOR_MAP_SWIZZLE_128B,
        CU_TENSOR_MAP_L2_PROMOTION_L2_128B, CU_TENSOR_MAP_FLOAT_OOB_FILL_NONE);
}

extern "C" void kernel_launch(void* const* d_in, const int* in_sizes, int n_in,
                              void* d_out, int out_size) {
    const float* sup    = (const float*)d_in[0];
    const float* qt     = (const float*)d_in[1];
    const float* st     = (const float*)d_in[2];
    const float* cls    = (const float*)d_in[3];
    const float* tfreq  = (const float*)d_in[4];
    const float* tphase = (const float*)d_in[5];
    const float* Wq = (const float*)d_in[6];
    const float* bq = (const float*)d_in[7];
    const float* Wk = (const float*)d_in[8];
    const float* bk = (const float*)d_in[9];
    const float* Wv = (const float*)d_in[10];
    const float* bv = (const float*)d_in[11];
    const float* Wo = (const float*)d_in[12];
    const float* bo = (const float*)d_in[13];
    const float* ln1g = (const float*)d_in[14];
    const float* ln1b = (const float*)d_in[15];
    const float* tw   = (const float*)d_in[16];
    const float* W1 = (const float*)d_in[17];
    const float* b1 = (const float*)d_in[18];
    const float* W2 = (const float*)d_in[19];
    const float* b2 = (const float*)d_in[20];
    const float* ln2g = (const float*)d_in[21];
    const float* ln2b = (const float*)d_in[22];
    const float* Wc = (const float*)d_in[23];
    const float* bc = (const float*)d_in[24];
    const float* bng = (const float*)d_in[25];
    const float* bnb = (const float*)d_in[26];
    float* out = (float*)d_out;

    float *X, *Tmp, *Out1, *Hc, *Bias, *bQKVp;
    __half *X16, *QKV16, *Ctx16, *O116, *Ffn16, *WQKVh, *Woh, *W1h, *W2h;
    cudaGetSymbolAddress((void**)&X,     g_X);
    cudaGetSymbolAddress((void**)&X16,   g_X16);
    cudaGetSymbolAddress((void**)&QKV16, g_QKV16);
    cudaGetSymbolAddress((void**)&Ctx16, g_Ctx16);
    cudaGetSymbolAddress((void**)&Tmp,   g_Tmp);
    cudaGetSymbolAddress((void**)&Out1,  g_Out1);
    cudaGetSymbolAddress((void**)&O116,  g_O116);
    cudaGetSymbolAddress((void**)&Ffn16, g_Ffn16);
    cudaGetSymbolAddress((void**)&Hc,    g_Hc);
    cudaGetSymbolAddress((void**)&Bias,  g_Bias);
    cudaGetSymbolAddress((void**)&bQKVp, g_bQKV);
    cudaGetSymbolAddress((void**)&WQKVh, g_WQKVh);
    cudaGetSymbolAddress((void**)&Woh,   g_Woh);
    cudaGetSymbolAddress((void**)&W1h,   g_W1h);
    cudaGetSymbolAddress((void**)&W2h,   g_W2h);

    // driver entry point for tensormap encode (no -lcuda at link time)
    PFN_tmencode enc = nullptr;
    {
        void* p = nullptr;
        cudaDriverEntryPointQueryResult qr;
        cudaGetDriverEntryPointByVersion("cuTensorMapEncodeTiled", &p, 12000,
                                         cudaEnableDefault, &qr);
        if (!p)
            cudaGetDriverEntryPoint("cuTensorMapEncodeTiled", &p, cudaEnableDefault, &qr);
        enc = (PFN_tmencode)p;
    }

    cudaFuncSetAttribute(hgemm_kernel,
                         cudaFuncAttributeMaxDynamicSharedMemorySize, HG_SMEM);

    CUtensorMap mX, mCtx, mO1, mFfn, mWqkv, mWo, mW1, mW2;
    make_map_h16(enc, &mX,   X16,   Dn,   ROWSn, 1,  128);
    make_map_h16(enc, &mCtx, Ctx16, Dn,   ROWSn, 1,  128);
    make_map_h16(enc, &mO1,  O116,  Dn,   ROWSn, 1,  128);
    make_map_h16(enc, &mFfn, Ffn16, FFNn, ROWSn, 1,  128);
    make_map_h16(enc, &mWqkv, WQKVh, Dn,   1536, Ln, 256);
    make_map_h16(enc, &mWo,   Woh,   Dn,   Dn,   Ln, 256);
    make_map_h16(enc, &mW1,   W1h,   Dn,   FFNn, Ln, 256);
    make_map_h16(enc, &mW2,   W2h,   FFNn, Dn,   Ln, 256);

    pack_weights_kernel<<<Ln * 3072, dim3(32, 8)>>>(Wq, Wk, Wv, Wo, W1, W2);
    pack_bias_kernel<<<12, 256>>>(bq, bk, bv);
    prep_x_kernel<<<ROWSn, 128>>>(sup, cls);
    prep_t_kernel<<<16, 256>>>(qt, st);
    prep_bias_kernel<<<BQn, 64>>>(tfreq, tphase, tw);

    const dim3 gQKV(1536 / 256, ROWSn / 128);   // 6 x 256
    const dim3 gD(Dn / 256, ROWSn / 128);       // 2 x 256
    const dim3 gF(FFNn / 256, ROWSn / 128);     // 8 x 256

    for (int l = 0; l < Ln; l++) {
        const float* bqkv = bQKVp + (size_t)l * 1536;

        hgemm_kernel<<<gQKV, 256, HG_SMEM>>>(mX, mWqkv, bqkv, nullptr, QKV16, 1536, Dn / 64, l, 0);

        attn_kernel<<<BQn * 4, 128>>>(Bias + (size_t)l * BQn * 64);

        hgemm_kernel<<<gD, 256, HG_SMEM>>>(mCtx, mWo, bo + l * Dn, Tmp, nullptr, Dn, Dn / 64, l, 0);
        add_ln_kernel<<<ROWSn, 256>>>(X, Tmp, ln1g + l * Dn, ln1b + l * Dn, Out1, O116);

        hgemm_kernel<<<gF, 256, HG_SMEM>>>(mO1, mW1, b1 + l * FFNn, nullptr, Ffn16, FFNn, Dn / 64, l, 1);
        hgemm_kernel<<<gD, 256, HG_SMEM>>>(mFfn, mW2, b2 + l * Dn, Tmp, nullptr, Dn, FFNn / 64, l, 0);
        add_ln_kernel<<<ROWSn, 256>>>(Out1, Tmp, ln2g + l * Dn, ln2b + l * Dn, X, X16);
    }

    // compress: only s=0 rows feed the output (exact fp32 path)
    sgemm_kernel<<<dim3(1, 32), 256>>>(X, Wc, bc, Hc, BQn, MDn, Dn, Sn * Dn, 0);
    bn_zero_kernel<<<1, 1>>>();
    bn_reduce_kernel<<<256, 256>>>();
    bn_final_kernel<<<2048, 256>>>(bng, bnb, out);

    (void)in_sizes; (void)n_in; (void)out_size;
}

// round 9
// speedup vs baseline: 5.4406x; 1.0805x over previous
#include <cuda_runtime.h>
#include <cuda.h>
#include <cuda_fp16.h>
#include <math.h>
#include <stdint.h>

#define BQn   4096
#define Sn    8
#define Dn    512
#define MDn   128
#define Ln    6
#define FFNn  2048
#define TDn   32
#define ROWSn (BQn * Sn)          /* 32768 */
#define SCALE 0.17677669529663687f /* 32^-0.5 */

// ---------------- scratch (device globals; no allocation allowed) -----------
__device__ float  g_X    [ROWSn * Dn];
__device__ __align__(1024) __half g_X16  [ROWSn * Dn];
__device__ __align__(1024) __half g_QKV16[ROWSn * 3 * Dn];
__device__ __align__(1024) __half g_Ctx16[ROWSn * Dn];
__device__ float  g_Tmp  [ROWSn * Dn];
__device__ float  g_Out1 [ROWSn * Dn];
__device__ __align__(1024) __half g_O116 [ROWSn * Dn];
__device__ __align__(1024) __half g_Ffn16[ROWSn * FFNn];
__device__ float  g_Bias [Ln * BQn * 64];
__device__ float  g_Tseq [BQn * Sn];
__device__ float  g_Hc   [BQn * MDn];
__device__ float  g_Stats[2];
__device__ __align__(1024) __half g_WQKVh[Ln * 1536 * Dn];   /* [l][n(q|k|v)][k] */
__device__ float  g_bQKV [Ln * 1536];
__device__ __align__(1024) __half g_Woh  [Ln * Dn * Dn];     /* [l][n][k] */
__device__ __align__(1024) __half g_W1h  [Ln * FFNn * Dn];   /* [l][n][k] */
__device__ __align__(1024) __half g_W2h  [Ln * Dn * FFNn];   /* [l][n][k] */

// ---------------- helpers ----------------------------------------------------
__device__ __forceinline__ float gelu_tanh(float v) {
    return 0.5f * v * (1.f + tanhf(0.7978845608028654f * (v + 0.044715f * v * v * v)));
}
__device__ __forceinline__ uint32_t smem_u32(const void* p) {
    uint32_t a;
    asm("{ .reg .u64 t; cvta.to.shared.u64 t, %1; cvt.u32.u64 %0, t; }" : "=r"(a) : "l"(p));
    return a;
}

#define MBAR_INIT(addr, cnt) \
    asm volatile("mbarrier.init.shared.b64 [%0], %1;" :: "r"(addr), "r"((uint32_t)(cnt)) : "memory")
#define MBAR_EXPECT_TX(addr, bytes) \
    asm volatile("mbarrier.arrive.expect_tx.shared.b64 _, [%0], %1;" :: "r"(addr), "r"((uint32_t)(bytes)) : "memory")
#define MBAR_ARRIVE(addr) \
    asm volatile("mbarrier.arrive.shared.b64 _, [%0];" :: "r"(addr) : "memory")
#define MBAR_WAIT(addr, parity) do {                                                   \
    uint32_t _m = (addr); uint32_t _p = (parity); uint32_t _d;                         \
    asm volatile("{\n\t.reg .pred p;\n\t"                                              \
        "mbarrier.try_wait.parity.acquire.cta.shared::cta.b64 p, [%1], %2;\n\t"        \
        "selp.b32 %0, 1, 0, p;\n\t}" : "=r"(_d) : "r"(_m), "r"(_p) : "memory");        \
    if (!_d) {                                                                         \
        asm volatile("{\n\t.reg .pred P1;\n\t"                                         \
            "W_%=:\n\t"                                                                \
            "mbarrier.try_wait.parity.acquire.cta.shared::cta.b64 P1, [%0], %1, 0x989680;\n\t" \
            "@P1 bra.uni D_%=;\n\t"                                                    \
            "bra.uni W_%=;\n\t"                                                        \
            "D_%=:\n\t}" :: "r"(_m), "r"(_p) : "memory");                              \
    }                                                                                  \
} while (0)

#define TMA_LOAD_3D(smem, map, x, y, z, mbar)                                             \
    asm volatile("cp.async.bulk.tensor.3d.shared::cta.global.tile.mbarrier::complete_tx::bytes " \
                 "[%0], [%1, {%2, %3, %4}], [%5];"                                        \
                 :: "r"((uint32_t)(smem)), "l"(map), "r"((int)(x)), "r"((int)(y)),        \
                    "r"((int)(z)), "r"((uint32_t)(mbar)) : "memory")

__device__ __forceinline__ void ldmx4(uint32_t& r0, uint32_t& r1, uint32_t& r2, uint32_t& r3,
                                      uint32_t addr) {
    asm volatile("ldmatrix.sync.aligned.m8n8.x4.shared.b16 {%0,%1,%2,%3}, [%4];"
                 : "=r"(r0), "=r"(r1), "=r"(r2), "=r"(r3) : "r"(addr));
}
__device__ __forceinline__ void mma_f16(float* c, const uint32_t* a, const uint32_t* b) {
    asm volatile(
        "mma.sync.aligned.m16n8k16.row.col.f32.f16.f16.f32 "
        "{%0,%1,%2,%3}, {%4,%5,%6,%7}, {%8,%9}, {%0,%1,%2,%3};"
        : "+f"(c[0]), "+f"(c[1]), "+f"(c[2]), "+f"(c[3])
        : "r"(a[0]), "r"(a[1]), "r"(a[2]), "r"(a[3]), "r"(b[0]), "r"(b[1]));
}

// ---------------- fp16 TMA + mma.sync GEMM -----------------------------------
// C[M,N] = A[M,K] @ Bt[N,K]^T + bias.  CTA 128x128, 4 warps (2x2),
// warp tile 64x64.  K chunks of 64 halves (128B rows, SW128), 3-stage TMA.
// 2 CTAs per SM (sibling covers TMA latency).  Stage: A 16KB + B 16KB.
#define NSTG     3
#define STG_BYT  32768
#define HG_SMEM  (NSTG * STG_BYT + 1024)

__global__ __launch_bounds__(128, 2)
void hgemm_kernel(const __grid_constant__ CUtensorMap tmA,
                  const __grid_constant__ CUtensorMap tmB,
                  const float* __restrict__ bias, float* __restrict__ Cf,
                  __half* __restrict__ Ch,
                  int N, int nKt, int layer, int act) {
    extern __shared__ char smraw[];
    __shared__ __align__(8) uint64_t mbar[2 * NSTG];
    uint32_t sb = (smem_u32(smraw) + 1023u) & ~1023u;
    uint32_t mbF = smem_u32(&mbar[0]);
    uint32_t mbE = smem_u32(&mbar[NSTG]);

    const int tid  = threadIdx.x;
    const int lane = tid & 31, warp = tid >> 5;
    const int wm = warp & 1, wn = warp >> 1;
    const int qr = lane >> 2, qc = lane & 3;
    const int jj = lane >> 3, rr = lane & 7;
    const int rowBase = blockIdx.y * 128;
    const int colBase = blockIdx.x * 128;

    if (tid == 0) {
#pragma unroll
        for (int s = 0; s < NSTG; s++) {
            MBAR_INIT(mbF + s * 8, 1);
            MBAR_INIT(mbE + s * 8, 128);
        }
    }
    __syncthreads();

    if (tid == 0) {
        int pre = nKt < NSTG ? nKt : NSTG;
        for (int s = 0; s < pre; s++) {
            MBAR_EXPECT_TX(mbF + s * 8, STG_BYT);
            TMA_LOAD_3D(sb + s * STG_BYT,         &tmA, s * 64, rowBase, 0,     mbF + s * 8);
            TMA_LOAD_3D(sb + s * STG_BYT + 16384, &tmB, s * 64, colBase, layer, mbF + s * 8);
        }
    }

    float acc[4][8][4];
#pragma unroll
    for (int i = 0; i < 4; i++)
#pragma unroll
        for (int j = 0; j < 8; j++)
#pragma unroll
            for (int k = 0; k < 4; k++) acc[i][j][k] = 0.f;

    // ldmatrix swizzled addressing: addr = base + row*128 + (colb ^ (rr<<4))
    const uint32_t xorv = (uint32_t)rr << 4;
    uint32_t a_row[4], b_row[4];
#pragma unroll
    for (int mt = 0; mt < 4; mt++)
        a_row[mt] = (uint32_t)(wm * 64 + mt * 16 + (jj & 1) * 8 + rr) * 128;
#pragma unroll
    for (int p = 0; p < 4; p++)
        b_row[p] = 16384u + (uint32_t)(wn * 64 + p * 16 + (jj & 1) * 8 + rr) * 128;
    const uint32_t colq = (uint32_t)(jj >> 1) * 16;

    for (int kt = 0; kt < nKt; kt++) {
        int stg = kt;
        while (stg >= NSTG) stg -= NSTG;          // kt % 3 without div
        int ph = (kt / NSTG) & 1;
        MBAR_WAIT(mbF + stg * 8, ph);
        uint32_t stage = sb + stg * STG_BYT;

#pragma unroll
        for (int kc = 0; kc < 4; kc++) {
            uint32_t colb = (kc * 32 + colq) ^ xorv;
            uint32_t af[4][4];
#pragma unroll
            for (int mt = 0; mt < 4; mt++)
                ldmx4(af[mt][0], af[mt][1], af[mt][2], af[mt][3], stage + a_row[mt] + colb);
            uint32_t bf[8][2];
#pragma unroll
            for (int p = 0; p < 4; p++) {
                uint32_t r0, r1, r2, r3;
                ldmx4(r0, r1, r2, r3, stage + b_row[p] + colb);
                bf[2 * p][0] = r0; bf[2 * p + 1][0] = r1;
                bf[2 * p][1] = r2; bf[2 * p + 1][1] = r3;
            }
#pragma unroll
            for (int mt = 0; mt < 4; mt++)
#pragma unroll
                for (int nt = 0; nt < 8; nt++)
                    mma_f16(acc[mt][nt], af[mt], bf[nt]);
        }
        MBAR_ARRIVE(mbE + stg * 8);
        if (tid == 0 && kt + NSTG < nKt) {
            MBAR_WAIT(mbE + stg * 8, ph);
            MBAR_EXPECT_TX(mbF + stg * 8, STG_BYT);
            TMA_LOAD_3D(sb + stg * STG_BYT,         &tmA, (kt + NSTG) * 64, rowBase, 0,     mbF + stg * 8);
            TMA_LOAD_3D(sb + stg * STG_BYT + 16384, &tmB, (kt + NSTG) * 64, colBase, layer, mbF + stg * 8);
        }
    }

    // ---- epilogue ----
#pragma unroll
    for (int mt = 0; mt < 4; mt++) {
        int row0 = rowBase + wm * 64 + mt * 16 + qr;
#pragma unroll
        for (int nt = 0; nt < 8; nt++) {
            int col = colBase + wn * 64 + nt * 8 + qc * 2;
            float b0 = bias[col], b1 = bias[col + 1];
            float v0 = acc[mt][nt][0] + b0;
            float v1 = acc[mt][nt][1] + b1;
            float v2 = acc[mt][nt][2] + b0;
            float v3 = acc[mt][nt][3] + b1;
            if (act) { v0 = gelu_tanh(v0); v1 = gelu_tanh(v1); v2 = gelu_tanh(v2); v3 = gelu_tanh(v3); }
            if (Cf) {
                *(float2*)(Cf + (size_t)row0 * N + col)       = make_float2(v0, v1);
                *(float2*)(Cf + (size_t)(row0 + 8) * N + col) = make_float2(v2, v3);
            }
            if (Ch) {
                *(__half2*)(Ch + (size_t)row0 * N + col)       = __floats2half2_rn(v0, v1);
                *(__half2*)(Ch + (size_t)(row0 + 8) * N + col) = __floats2half2_rn(v2, v3);
            }
        }
    }
}

// ---------------- weight packing: transpose [K][N] f32 -> [N][K] half --------
__global__ void pack_weights_kernel(const float* __restrict__ Wq, const float* __restrict__ Wk,
                                    const float* __restrict__ Wv, const float* __restrict__ Wo,
                                    const float* __restrict__ W1, const float* __restrict__ W2) {
    __shared__ float t[32][33];
    int bid = blockIdx.x;
    int l = bid / 3072, tt = bid % 3072;
    const float* src; __half* dst; int Kd, Nd, tk, tn;
    if (tt < 768) {
        int which = tt / 256, r = tt % 256;
        src = (which == 0 ? Wq : which == 1 ? Wk : Wv) + (size_t)l * Dn * Dn;
        dst = g_WQKVh + (size_t)l * 1536 * Dn + (size_t)which * Dn * Dn;
        Kd = Dn; Nd = Dn; tk = r & 15; tn = r >> 4;
    } else if (tt < 1024) {
        int r = tt - 768;
        src = Wo + (size_t)l * Dn * Dn;
        dst = g_Woh + (size_t)l * Dn * Dn;
        Kd = Dn; Nd = Dn; tk = r & 15; tn = r >> 4;
    } else if (tt < 2048) {
        int r = tt - 1024;
        src = W1 + (size_t)l * Dn * FFNn;
        dst = g_W1h + (size_t)l * FFNn * Dn;
        Kd = Dn; Nd = FFNn; tk = r & 15; tn = r >> 4;
    } else {
        int r = tt - 2048;
        src = W2 + (size_t)l * FFNn * Dn;
        dst = g_W2h + (size_t)l * Dn * FFNn;
        Kd = FFNn; Nd = Dn; tk = r & 63; tn = r >> 6;
    }
    int k0 = tk * 32, n0 = tn * 32;
    int x = threadIdx.x, y = threadIdx.y;
#pragma unroll
    for (int i = 0; i < 32; i += 8)
        t[y + i][x] = src[(size_t)(k0 + y + i) * Nd + n0 + x];
    __syncthreads();
#pragma unroll
    for (int i = 0; i < 32; i += 8)
        dst[(size_t)(n0 + y + i) * Kd + k0 + x] = __float2half(t[x][y + i]);
}

__global__ void pack_bias_kernel(const float* __restrict__ bq, const float* __restrict__ bk,
                                 const float* __restrict__ bv) {
    int m = blockIdx.x * blockDim.x + threadIdx.x;
    if (m < Ln * Dn) {
        int l = m / Dn, c = m % Dn;
        g_bQKV[l * 1536 + c]        = bq[m];
        g_bQKV[l * 1536 + 512 + c]  = bk[m];
        g_bQKV[l * 1536 + 1024 + c] = bv[m];
    }
}

// ---------------- prep kernels ----------------------------------------------
__global__ void prep_x_kernel(const float* __restrict__ sup,
                              const float* __restrict__ cls) {
    int row = blockIdx.x;
    int s   = row & 7;
    int bq  = row >> 3;
    int b   = bq >> 5;
    int t   = threadIdx.x;
    float v = (s == 0) ? cls[t] : sup[(b * 7 + (s - 1)) * MDn + t];
    __half h = __float2half(v);
#pragma unroll
    for (int hh = 0; hh < 4; hh++) {
        g_X  [row * Dn + hh * MDn + t] = v;
        g_X16[row * Dn + hh * MDn + t] = h;
    }
}

__global__ void prep_t_kernel(const float* __restrict__ query_t,
                              const float* __restrict__ support_t) {
    int bq = blockIdx.x * blockDim.x + threadIdx.x;
    if (bq >= BQn) return;
    int b = bq >> 5, q = bq & 31;
    g_Tseq[bq * 8] = query_t[b * 32 + q];
#pragma unroll
    for (int f = 0; f < 7; f++)
        g_Tseq[bq * 8 + 1 + f] = support_t[b * 7 + f];
}

__global__ void prep_bias_kernel(const float* __restrict__ t_freq,
                                 const float* __restrict__ t_phase,
                                 const float* __restrict__ time_w) {
    int bq  = blockIdx.x;
    int tid = threadIdx.x;             // 64
    __shared__ float tw[Ln][TDn];
    __shared__ float fr[TDn], ph[TDn], ts[Sn];
    if (tid < TDn) { fr[tid] = t_freq[tid]; ph[tid] = t_phase[tid]; }
    if (tid < Sn)  ts[tid] = g_Tseq[bq * 8 + tid];
    for (int i = tid; i < Ln * TDn; i += 64) tw[i / TDn][i % TDn] = time_w[i];
    __syncthreads();
    int s = tid >> 3, t = tid & 7;
    float dt = ts[s] - ts[t];
    float acc[Ln];
#pragma unroll
    for (int l = 0; l < Ln; l++) acc[l] = 0.f;
    for (int td = 0; td < TDn; td++) {
        float c = cosf(dt * fr[td] + ph[td]);
#pragma unroll
        for (int l = 0; l < Ln; l++) acc[l] += c * tw[l][td];
    }
#pragma unroll
    for (int l = 0; l < Ln; l++)
        g_Bias[(l * BQn + bq) * 64 + tid] = acc[l];
}

// ---------------- fp32 SGEMM (small Wc projection only) ---------------------
__global__ __launch_bounds__(256, 2)
void sgemm_kernel(const float* __restrict__ A, const float* __restrict__ W,
                  const float* __restrict__ bias, float* __restrict__ C,
                  int M, int N, int K, int lda, int act) {
    __shared__ float As[8][128];
    __shared__ float Bs[8][128];
    const int tid = threadIdx.x;
    const int rowBase = blockIdx.y * 128;
    const int colBase = blockIdx.x * 128;
    const int ty = tid >> 4, tx = tid & 15;

    const int aRow = tid >> 1;
    const int aK   = (tid & 1) * 4;
    const int bRow = tid >> 5;
    const int bC4  = (tid & 31) * 4;
    const float* Ap = A + (rowBase + aRow) * lda + aK;
    const float* Wp = W + bRow * N + colBase + bC4;

    float acc[8][8];
#pragma unroll
    for (int i = 0; i < 8; i++)
#pragma unroll
        for (int j = 0; j < 8; j++) acc[i][j] = 0.f;

    for (int k0 = 0; k0 < K; k0 += 8) {
        float4 a = *(const float4*)(Ap + k0);
        As[aK + 0][aRow] = a.x;
        As[aK + 1][aRow] = a.y;
        As[aK + 2][aRow] = a.z;
        As[aK + 3][aRow] = a.w;
        *(float4*)&Bs[bRow][bC4] = *(const float4*)(Wp + (size_t)k0 * N);
        __syncthreads();
#pragma unroll
        for (int kk = 0; kk < 8; kk++) {
            float ra[8], rb[8];
#pragma unroll
            for (int i = 0; i < 8; i++) ra[i] = As[kk][ty * 8 + i];
#pragma unroll
            for (int j = 0; j < 4; j++) {
                rb[j]     = Bs[kk][tx * 4 + j];
                rb[j + 4] = Bs[kk][64 + tx * 4 + j];
            }
#pragma unroll
            for (int i = 0; i < 8; i++)
#pragma unroll
                for (int j = 0; j < 8; j++) acc[i][j] = fmaf(ra[i], rb[j], acc[i][j]);
        }
        __syncthreads();
    }
#pragma unroll
    for (int i = 0; i < 8; i++) {
        int row = rowBase + ty * 8 + i;
#pragma unroll
        for (int j = 0; j < 8; j++) {
            int col = colBase + ((j < 4) ? (tx * 4 + j) : (64 + tx * 4 + j - 4));
            float v = acc[i][j] + bias[col];
            if (act) {
                float x3 = v * v * v;
                v = 0.5f * v * (1.f + tanhf(0.7978845608028654f * (v + 0.044715f * x3)));
            }
            C[(size_t)row * N + col] = v;
        }
    }
}

// ---------------- attention on fused fp16 QKV buffer -------------------------
__global__ void attn_kernel(const float* __restrict__ bias) {
    int j   = blockIdx.x;              // 0..BQ*H-1
    int tid = threadIdx.x;             // 128
    __shared__ float qs[8][128], ks[8][128], vs[8][128];
    __shared__ float sc[8][9];
    const __half* base = g_QKV16 + (size_t)(j * 2) * 1536;  // raw reshape: j*1024 elems = 2 rows
#pragma unroll
    for (int s = 0; s < 8; s++) {
        int off = s * 128 + tid;
        int r = off >> 9, c = off & 511;
        const __half* rp = base + (size_t)r * 1536 + c;
        qs[s][tid] = __half2float(rp[0]);
        ks[s][tid] = __half2float(rp[512]);
        vs[s][tid] = __half2float(rp[1024]);
    }
    __syncthreads();
    if (tid < 64) {
        int s = tid >> 3, t = tid & 7;
        float d = 0.f;
#pragma unroll
        for (int i = 0; i < 128; i++) d = fmaf(qs[s][i], ks[t][i], d);
        sc[s][t] = d * SCALE + bias[(j & (BQn - 1)) * 64 + tid];
    }
    __syncthreads();
    if (tid < 8) {
        int s = tid;
        float m = sc[s][0];
#pragma unroll
        for (int t = 1; t < 8; t++) m = fmaxf(m, sc[s][t]);
        float sum = 0.f;
#pragma unroll
        for (int t = 0; t < 8; t++) { float e = expf(sc[s][t] - m); sc[s][t] = e; sum += e; }
        float inv = 1.f / sum;
#pragma unroll
        for (int t = 0; t < 8; t++) sc[s][t] *= inv;
    }
    __syncthreads();
    __half* cp = g_Ctx16 + (size_t)j * 1024;
#pragma unroll
    for (int s = 0; s < 8; s++) {
        float a = 0.f;
#pragma unroll
        for (int t = 0; t < 8; t++) a = fmaf(sc[s][t], vs[t][tid], a);
        cp[s * 128 + tid] = __float2half(a);
    }
}

// ---------------- residual add + LayerNorm: warp-per-row, no block barrier ---
__global__ __launch_bounds__(256)
void add_ln_kernel(const float* __restrict__ res, const float* __restrict__ add,
                   const float* __restrict__ g, const float* __restrict__ b,
                   float* __restrict__ out, __half* __restrict__ out16) {
    int row  = blockIdx.x * 8 + (threadIdx.x >> 5);
    int lane = threadIdx.x & 31;
    const float4* rp = (const float4*)(res + (size_t)row * Dn);
    const float4* ap = (const float4*)(add + (size_t)row * Dn);
    float4 v[4];
    float s = 0.f, sq = 0.f;
#pragma unroll
    for (int i = 0; i < 4; i++) {
        float4 r = rp[i * 32 + lane];
        float4 a = ap[i * 32 + lane];
        v[i].x = r.x + a.x; v[i].y = r.y + a.y;
        v[i].z = r.z + a.z; v[i].w = r.w + a.w;
        s  += v[i].x + v[i].y + v[i].z + v[i].w;
        sq += v[i].x * v[i].x + v[i].y * v[i].y + v[i].z * v[i].z + v[i].w * v[i].w;
    }
#pragma unroll
    for (int o = 16; o > 0; o >>= 1) {
        s  += __shfl_xor_sync(0xffffffffu, s,  o);
        sq += __shfl_xor_sync(0xffffffffu, sq, o);
    }
    float mean = s * (1.f / Dn);
    float inv  = rsqrtf(sq * (1.f / Dn) - mean * mean + 1e-5f);
    float4* op = (float4*)(out + (size_t)row * Dn);
    __half2* hp = (__half2*)(out16 + (size_t)row * Dn);
#pragma unroll
    for (int i = 0; i < 4; i++) {
        int c = (i * 32 + lane) * 4;
        float o0 = g[c + 0] * (v[i].x - mean) * inv + b[c + 0];
        float o1 = g[c + 1] * (v[i].y - mean) * inv + b[c + 1];
        float o2 = g[c + 2] * (v[i].z - mean) * inv + b[c + 2];
        float o3 = g[c + 3] * (v[i].w - mean) * inv + b[c + 3];
        op[i * 32 + lane] = make_float4(o0, o1, o2, o3);
        hp[(i * 32 + lane) * 2]     = __floats2half2_rn(o0, o1);
        hp[(i * 32 + lane) * 2 + 1] = __floats2half2_rn(o2, o3);
    }
}

// ---------------- final BatchNorm (only s=0 channel needed) -----------------
__global__ void bn_zero_kernel() { g_Stats[0] = 0.f; g_Stats[1] = 0.f; }

__global__ void bn_reduce_kernel() {
    float s = 0.f, q = 0.f;
    for (int i = blockIdx.x * blockDim.x + threadIdx.x; i < BQn * MDn;
         i += gridDim.x * blockDim.x) {
        float v = g_Hc[i]; s += v; q += v * v;
    }
#pragma unroll
    for (int o = 16; o > 0; o >>= 1) {
        s += __shfl_xor_sync(0xffffffffu, s, o);
        q += __shfl_xor_sync(0xffffffffu, q, o);
    }
    __shared__ float rs[8], rq[8];
    int w = threadIdx.x >> 5;
    if ((threadIdx.x & 31) == 0) { rs[w] = s; rq[w] = q; }
    __syncthreads();
    if (threadIdx.x == 0) {
        float ts = 0.f, tq = 0.f;
#pragma unroll
        for (int i = 0; i < 8; i++) { ts += rs[i]; tq += rq[i]; }
        atomicAdd(&g_Stats[0], ts);
        atomicAdd(&g_Stats[1], tq);
    }
}

__global__ void bn_final_kernel(const float* __restrict__ bn_g,
                                const float* __restrict__ bn_b,
                                float* __restrict__ out) {
    const float invN = 1.f / (float)(BQn * MDn);
    float mu  = g_Stats[0] * invN;
    float var = g_Stats[1] * invN - mu * mu;
    float inv = rsqrtf(var + 1e-5f);
    float gg = bn_g[0], bb = bn_b[0];
    for (int i = blockIdx.x * blockDim.x + threadIdx.x; i < BQn * MDn;
         i += gridDim.x * blockDim.x) {
        float h = gg * (g_Hc[i] - mu) * inv + bb;
        out[i] = (h >= 0.f) ? h : 0.01f * h;
    }
}

// ---------------- host orchestration ----------------------------------------
typedef CUresult (*PFN_tmencode)(
    CUtensorMap*, CUtensorMapDataType, cuuint32_t, void*,
    const cuuint64_t*, const cuuint64_t*, const cuuint32_t*, const cuuint32_t*,
    CUtensorMapInterleave, CUtensorMapSwizzle, CUtensorMapL2promotion,
    CUtensorMapFloatOOBfill);

static void make_map_h16(PFN_tmencode enc, CUtensorMap* m, void* ptr,
                         unsigned long long K, unsigned long long rows,
                         unsigned long long L) {
    cuuint64_t dims[3]    = {K, rows, L};
    cuuint64_t strides[2] = {K * 2ull, rows * K * 2ull};
    cuuint32_t box[3]     = {64u, 128u, 1u};
    cuuint32_t es[3]      = {1u, 1u, 1u};
    enc(m, CU_TENSOR_MAP_DATA_TYPE_UINT16, 3, ptr, dims, strides, box, es,
        CU_TENSOR_MAP_INTERLEAVE_NONE, CU_TENSOR_MAP_SWIZZLE_128B,
        CU_TENSOR_MAP_L2_PROMOTION_L2_128B, CU_TENSOR_MAP_FLOAT_OOB_FILL_NONE);
}

extern "C" void kernel_launch(void* const* d_in, const int* in_sizes, int n_in,
                              void* d_out, int out_size) {
    const float* sup    = (const float*)d_in[0];
    const float* qt     = (const float*)d_in[1];
    const float* st     = (const float*)d_in[2];
    const float* cls    = (const float*)d_in[3];
    const float* tfreq  = (const float*)d_in[4];
    const float* tphase = (const float*)d_in[5];
    const float* Wq = (const float*)d_in[6];
    const float* bq = (const float*)d_in[7];
    const float* Wk = (const float*)d_in[8];
    const float* bk = (const float*)d_in[9];
    const float* Wv = (const float*)d_in[10];
    const float* bv = (const float*)d_in[11];
    const float* Wo = (const float*)d_in[12];
    const float* bo = (const float*)d_in[13];
    const float* ln1g = (const float*)d_in[14];
    const float* ln1b = (const float*)d_in[15];
    const float* tw   = (const float*)d_in[16];
    const float* W1 = (const float*)d_in[17];
    const float* b1 = (const float*)d_in[18];
    const float* W2 = (const float*)d_in[19];
    const float* b2 = (const float*)d_in[20];
    const float* ln2g = (const float*)d_in[21];
    const float* ln2b = (const float*)d_in[22];
    const float* Wc = (const float*)d_in[23];
    const float* bc = (const float*)d_in[24];
    const float* bng = (const float*)d_in[25];
    const float* bnb = (const float*)d_in[26];
    float* out = (float*)d_out;

    float *X, *Tmp, *Out1, *Hc, *Bias, *bQKVp;
    __half *X16, *QKV16, *Ctx16, *O116, *Ffn16, *WQKVh, *Woh, *W1h, *W2h;
    cudaGetSymbolAddress((void**)&X,     g_X);
    cudaGetSymbolAddress((void**)&X16,   g_X16);
    cudaGetSymbolAddress((void**)&QKV16, g_QKV16);
    cudaGetSymbolAddress((void**)&Ctx16, g_Ctx16);
    cudaGetSymbolAddress((void**)&Tmp,   g_Tmp);
    cudaGetSymbolAddress((void**)&Out1,  g_Out1);
    cudaGetSymbolAddress((void**)&O116,  g_O116);
    cudaGetSymbolAddress((void**)&Ffn16, g_Ffn16);
    cudaGetSymbolAddress((void**)&Hc,    g_Hc);
    cudaGetSymbolAddress((void**)&Bias,  g_Bias);
    cudaGetSymbolAddress((void**)&bQKVp, g_bQKV);
    cudaGetSymbolAddress((void**)&WQKVh, g_WQKVh);
    cudaGetSymbolAddress((void**)&Woh,   g_Woh);
    cudaGetSymbolAddress((void**)&W1h,   g_W1h);
    cudaGetSymbolAddress((void**)&W2h,   g_W2h);

    // driver entry point for tensormap encode (no -lcuda at link time)
    PFN_tmencode enc = nullptr;
    {
        void* p = nullptr;
        cudaDriverEntryPointQueryResult qr;
        cudaGetDriverEntryPointByVersion("cuTensorMapEncodeTiled", &p, 12000,
                                         cudaEnableDefault, &qr);
        if (!p)
            cudaGetDriverEntryPoint("cuTensorMapEncodeTiled", &p, cudaEnableDefault, &qr);
        enc = (PFN_tmencode)p;
    }

    cudaFuncSetAttribute(hgemm_kernel,
                         cudaFuncAttributeMaxDynamicSharedMemorySize, HG_SMEM);

    CUtensorMap mX, mCtx, mO1, mFfn, mWqkv, mWo, mW1, mW2;
    make_map_h16(enc, &mX,   X16,   Dn,   ROWSn, 1);
    make_map_h16(enc, &mCtx, Ctx16, Dn,   ROWSn, 1);
    make_map_h16(enc, &mO1,  O116,  Dn,   ROWSn, 1);
    make_map_h16(enc, &mFfn, Ffn16, FFNn, ROWSn, 1);
    make_map_h16(enc, &mWqkv, WQKVh, Dn,   1536, Ln);
    make_map_h16(enc, &mWo,   Woh,   Dn,   Dn,   Ln);
    make_map_h16(enc, &mW1,   W1h,   Dn,   FFNn, Ln);
    make_map_h16(enc, &mW2,   W2h,   FFNn, Dn,   Ln);

    pack_weights_kernel<<<Ln * 3072, dim3(32, 8)>>>(Wq, Wk, Wv, Wo, W1, W2);
    pack_bias_kernel<<<12, 256>>>(bq, bk, bv);
    prep_x_kernel<<<ROWSn, 128>>>(sup, cls);
    prep_t_kernel<<<16, 256>>>(qt, st);
    prep_bias_kernel<<<BQn, 64>>>(tfreq, tphase, tw);

    const dim3 gQKV(1536 / 128, ROWSn / 128);   // 12 x 256
    const dim3 gD(Dn / 128, ROWSn / 128);       // 4 x 256
    const dim3 gF(FFNn / 128, ROWSn / 128);     // 16 x 256

    for (int l = 0; l < Ln; l++) {
        const float* bqkv = bQKVp + (size_t)l * 1536;

        hgemm_kernel<<<gQKV, 128, HG_SMEM>>>(mX, mWqkv, bqkv, nullptr, QKV16, 1536, Dn / 64, l, 0);

        attn_kernel<<<BQn * 4, 128>>>(Bias + (size_t)l * BQn * 64);

        hgemm_kernel<<<gD, 128, HG_SMEM>>>(mCtx, mWo, bo + l * Dn, Tmp, nullptr, Dn, Dn / 64, l, 0);
        add_ln_kernel<<<ROWSn / 8, 256>>>(X, Tmp, ln1g + l * Dn, ln1b + l * Dn, Out1, O116);

        hgemm_kernel<<<gF, 128, HG_SMEM>>>(mO1, mW1, b1 + l * FFNn, nullptr, Ffn16, FFNn, Dn / 64, l, 1);
        hgemm_kernel<<<gD, 128, HG_SMEM>>>(mFfn, mW2, b2 + l * Dn, Tmp, nullptr, Dn, FFNn / 64, l, 0);
        add_ln_kernel<<<ROWSn / 8, 256>>>(Out1, Tmp, ln2g + l * Dn, ln2b + l * Dn, X, X16);
    }

    // compress: only s=0 rows feed the output (exact fp32 path)
    sgemm_kernel<<<dim3(1, 32), 256>>>(X, Wc, bc, Hc, BQn, MDn, Dn, Sn * Dn, 0);
    bn_zero_kernel<<<1, 1>>>();
    bn_reduce_kernel<<<256, 256>>>();
    bn_final_kernel<<<2048, 256>>>(bng, bnb, out);

    (void)in_sizes; (void)n_in; (void)out_size;
}